// round 2
// baseline (speedup 1.0000x reference)
#include <cuda_runtime.h>
#include <cuda_bf16.h>
#include <cstdint>

// Problem constants: B=1, H=128, S=256, D=2048, fp32 everywhere.
#define HH 128
#define SS 256
#define DD 2048

#define TS 64
#define KC 16

// 33.5 MB scratch for attention probabilities (alloc in kernel_launch is banned).
__device__ float g_attn[(size_t)HH * SS * SS];

// ---------------------------------------------------------------------------
// Phase A: scores[h,q,k] = (Q[h,q,:] . K[h,k,:]) * scale + mask[q,k]
// 64x64 tile per block, K-loop over D=2048 in chunks of 16. 256 threads, 4x4/thread.
// ---------------------------------------------------------------------------
__global__ __launch_bounds__(256) void qk_kernel(
    const float* __restrict__ Q, const float* __restrict__ K,
    const float* __restrict__ mask, float* __restrict__ attn) {
  const int h  = blockIdx.z;
  const int q0 = blockIdx.y * TS;
  const int k0 = blockIdx.x * TS;
  const float* Qh = Q + (size_t)h * SS * DD;
  const float* Kh = K + (size_t)h * SS * DD;

  __shared__ float As[KC][TS + 1];
  __shared__ float Bs[KC][TS + 1];

  const int tid = threadIdx.x;
  const int tx = tid & 15;
  const int ty = tid >> 4;

  // load mapping: 64 rows x 16 k-values, float4 per thread
  const int lr = tid >> 2;         // 0..63
  const int lc = (tid & 3) * 4;    // 0,4,8,12

  float acc[4][4] = {};

  for (int kb = 0; kb < DD; kb += KC) {
    float4 a = *(const float4*)(Qh + (size_t)(q0 + lr) * DD + kb + lc);
    float4 b = *(const float4*)(Kh + (size_t)(k0 + lr) * DD + kb + lc);
    As[lc + 0][lr] = a.x; As[lc + 1][lr] = a.y; As[lc + 2][lr] = a.z; As[lc + 3][lr] = a.w;
    Bs[lc + 0][lr] = b.x; Bs[lc + 1][lr] = b.y; Bs[lc + 2][lr] = b.z; Bs[lc + 3][lr] = b.w;
    __syncthreads();
#pragma unroll
    for (int kk = 0; kk < KC; kk++) {
      float ar[4], br[4];
#pragma unroll
      for (int i = 0; i < 4; i++) { ar[i] = As[kk][ty * 4 + i]; br[i] = Bs[kk][tx * 4 + i]; }
#pragma unroll
      for (int i = 0; i < 4; i++)
#pragma unroll
        for (int j = 0; j < 4; j++) acc[i][j] += ar[i] * br[j];
    }
    __syncthreads();
  }

  const float scale = 0.022097086912079608f;  // 1/sqrt(2048)
#pragma unroll
  for (int i = 0; i < 4; i++) {
    const int q = q0 + ty * 4 + i;
#pragma unroll
    for (int j = 0; j < 4; j++) {
      const int k = k0 + tx * 4 + j;
      attn[((size_t)h * SS + q) * SS + k] = acc[i][j] * scale + mask[q * SS + k];
    }
  }
}

// ---------------------------------------------------------------------------
// JAX threefry2x32 — exact replica of jax._src.prng threefry2x32 (20 rounds).
// ---------------------------------------------------------------------------
__device__ __forceinline__ uint32_t rotl32(uint32_t x, int r) {
  return (x << r) | (x >> (32 - r));
}

__device__ __forceinline__ void threefry2x32(uint32_t k0, uint32_t k1,
                                             uint32_t& x0, uint32_t& x1) {
  const uint32_t ks0 = k0, ks1 = k1, ks2 = k0 ^ k1 ^ 0x1BD11BDAu;
  x0 += ks0; x1 += ks1;
#define TF_R(r) { x0 += x1; x1 = rotl32(x1, r); x1 ^= x0; }
  TF_R(13) TF_R(15) TF_R(26) TF_R(6)
  x0 += ks1; x1 += ks2 + 1u;
  TF_R(17) TF_R(29) TF_R(16) TF_R(24)
  x0 += ks2; x1 += ks0 + 2u;
  TF_R(13) TF_R(15) TF_R(26) TF_R(6)
  x0 += ks0; x1 += ks1 + 3u;
  TF_R(17) TF_R(29) TF_R(16) TF_R(24)
  x0 += ks1; x1 += ks2 + 4u;
  TF_R(13) TF_R(15) TF_R(26) TF_R(6)
  x0 += ks2; x1 += ks0 + 5u;
#undef TF_R
}

// ---------------------------------------------------------------------------
// Phase B: softmax along k (256 elems) + deterministic dropout (key 42, p=0.9).
// PARTITIONABLE threefry (JAX >= 0.4.36 default):
//   counts = iota(uint64); bits[i] = out0 ^ out1 of hash(hi32(i), lo32(i)).
// For size < 2^32: bits[i] = out0 ^ out1 of threefry2x32(key, (0, i)).
// One block of 256 threads per (h,q) row.
// ---------------------------------------------------------------------------
__global__ __launch_bounds__(256) void softmax_dropout_kernel(float* __restrict__ attn) {
  const int row = blockIdx.x;      // h*256 + q
  const int k = threadIdx.x;       // 0..255
  const size_t base = (size_t)row * SS;

  float v = attn[base + k];

  __shared__ float red[256];
  red[k] = v;
  __syncthreads();
#pragma unroll
  for (int s = 128; s > 0; s >>= 1) {
    if (k < s) red[k] = fmaxf(red[k], red[k + s]);
    __syncthreads();
  }
  const float m = red[0];
  __syncthreads();

  const float e = expf(v - m);
  red[k] = e;
  __syncthreads();
#pragma unroll
  for (int s = 128; s > 0; s >>= 1) {
    if (k < s) red[k] += red[k + s];
    __syncthreads();
  }
  float p = e / red[0];

  // Exact JAX bernoulli(key(42), 0.1, (1,128,256,256)) with partitionable threefry.
  const uint32_t i = (uint32_t)row * (uint32_t)SS + (uint32_t)k;
  uint32_t x0 = 0u, x1 = i;        // (hi32, lo32) of uint64 counter i
  threefry2x32(0u, 42u, x0, x1);
  const uint32_t bits = x0 ^ x1;
  const float u = __uint_as_float((bits >> 9) | 0x3F800000u) - 1.0f;

  p = (u < 0.1f) ? (p / 0.1f) : 0.0f;
  attn[base + k] = p;
}

// ---------------------------------------------------------------------------
// Phase C: out[h,q,d] = sum_k P[h,q,k] * V[h,k,d].
// 64(q) x 64(d) tile per block, K-loop over S=256 in chunks of 16.
// ---------------------------------------------------------------------------
__global__ __launch_bounds__(256) void pv_kernel(
    const float* __restrict__ P, const float* __restrict__ V,
    float* __restrict__ out) {
  const int h  = blockIdx.z;
  const int q0 = blockIdx.y * TS;
  const int d0 = blockIdx.x * TS;
  const float* Ph = P + (size_t)h * SS * SS;
  const float* Vh = V + (size_t)h * SS * DD;

  __shared__ float As[KC][TS + 1];   // As[kk][q]
  __shared__ float Bs[KC][TS];       // Bs[kk][d]

  const int tid = threadIdx.x;
  const int tx = tid & 15;
  const int ty = tid >> 4;

  const int ar = tid >> 2;          // P row 0..63
  const int ac = (tid & 3) * 4;     // P k-offset 0,4,8,12
  const int br = tid >> 4;          // V row 0..15
  const int bc = (tid & 15) * 4;    // V d-offset

  float acc[4][4] = {};

  for (int kb = 0; kb < SS; kb += KC) {
    float4 a = *(const float4*)(Ph + (size_t)(q0 + ar) * SS + kb + ac);
    As[ac + 0][ar] = a.x; As[ac + 1][ar] = a.y; As[ac + 2][ar] = a.z; As[ac + 3][ar] = a.w;
    float4 b = *(const float4*)(Vh + (size_t)(kb + br) * DD + d0 + bc);
    *(float4*)&Bs[br][bc] = b;
    __syncthreads();
#pragma unroll
    for (int kk = 0; kk < KC; kk++) {
      float av[4], bv[4];
#pragma unroll
      for (int i = 0; i < 4; i++) { av[i] = As[kk][ty * 4 + i]; bv[i] = Bs[kk][tx * 4 + i]; }
#pragma unroll
      for (int i = 0; i < 4; i++)
#pragma unroll
        for (int j = 0; j < 4; j++) acc[i][j] += av[i] * bv[j];
    }
    __syncthreads();
  }

#pragma unroll
  for (int i = 0; i < 4; i++) {
    const int q = q0 + ty * 4 + i;
#pragma unroll
    for (int j = 0; j < 4; j++) {
      const int d = d0 + tx * 4 + j;
      out[((size_t)h * SS + q) * DD + d] = acc[i][j];
    }
  }
}

// ---------------------------------------------------------------------------
// Launch
// ---------------------------------------------------------------------------
extern "C" void kernel_launch(void* const* d_in, const int* in_sizes, int n_in,
                              void* d_out, int out_size) {
  const float* Q    = (const float*)d_in[0];
  const float* K    = (const float*)d_in[1];
  const float* V    = (const float*)d_in[2];
  const float* mask = (const float*)d_in[3];
  float* out = (float*)d_out;

  float* attn = nullptr;
  cudaGetSymbolAddress((void**)&attn, g_attn);

  // QK^T * scale + mask
  qk_kernel<<<dim3(SS / TS, SS / TS, HH), 256>>>(Q, K, mask, attn);
  // softmax + exact threefry dropout (partitionable layout)
  softmax_dropout_kernel<<<HH * SS, 256>>>(attn);
  // P @ V
  pv_kernel<<<dim3(DD / TS, SS / TS, HH), 256>>>(attn, V, out);
}

// round 3
// speedup vs baseline: 1.0024x; 1.0024x over previous
#include <cuda_runtime.h>
#include <cuda_bf16.h>
#include <cstdint>

// Problem constants: B=1, H=128, S=256, D=2048, fp32 everywhere.
#define HH 128
#define SS 256
#define DD 2048

#define TS 64
#define KC 16

// 33.5 MB scratch for attention probabilities (alloc in kernel_launch is banned).
__device__ float g_attn[(size_t)HH * SS * SS];

// ---------------------------------------------------------------------------
// Phase A: scores[h,q,k] = (Q[h,q,:] . K[h,k,:]) * scale + mask[q,k]
// 64x64 tile per block, K-loop over D=2048 in chunks of 16. 256 threads, 4x4/thread.
// ---------------------------------------------------------------------------
__global__ __launch_bounds__(256) void qk_kernel(
    const float* __restrict__ Q, const float* __restrict__ K,
    const float* __restrict__ mask, float* __restrict__ attn) {
  const int h  = blockIdx.z;
  const int q0 = blockIdx.y * TS;
  const int k0 = blockIdx.x * TS;
  const float* Qh = Q + (size_t)h * SS * DD;
  const float* Kh = K + (size_t)h * SS * DD;

  __shared__ float As[KC][TS + 1];
  __shared__ float Bs[KC][TS + 1];

  const int tid = threadIdx.x;
  const int tx = tid & 15;
  const int ty = tid >> 4;

  // load mapping: 64 rows x 16 k-values, float4 per thread
  const int lr = tid >> 2;         // 0..63
  const int lc = (tid & 3) * 4;    // 0,4,8,12

  float acc[4][4] = {};

  for (int kb = 0; kb < DD; kb += KC) {
    float4 a = *(const float4*)(Qh + (size_t)(q0 + lr) * DD + kb + lc);
    float4 b = *(const float4*)(Kh + (size_t)(k0 + lr) * DD + kb + lc);
    As[lc + 0][lr] = a.x; As[lc + 1][lr] = a.y; As[lc + 2][lr] = a.z; As[lc + 3][lr] = a.w;
    Bs[lc + 0][lr] = b.x; Bs[lc + 1][lr] = b.y; Bs[lc + 2][lr] = b.z; Bs[lc + 3][lr] = b.w;
    __syncthreads();
#pragma unroll
    for (int kk = 0; kk < KC; kk++) {
      float ar[4], br[4];
#pragma unroll
      for (int i = 0; i < 4; i++) { ar[i] = As[kk][ty * 4 + i]; br[i] = Bs[kk][tx * 4 + i]; }
#pragma unroll
      for (int i = 0; i < 4; i++)
#pragma unroll
        for (int j = 0; j < 4; j++) acc[i][j] += ar[i] * br[j];
    }
    __syncthreads();
  }

  const float scale = 0.022097086912079608f;  // 1/sqrt(2048)
#pragma unroll
  for (int i = 0; i < 4; i++) {
    const int q = q0 + ty * 4 + i;
#pragma unroll
    for (int j = 0; j < 4; j++) {
      const int k = k0 + tx * 4 + j;
      attn[((size_t)h * SS + q) * SS + k] = acc[i][j] * scale + mask[q * SS + k];
    }
  }
}

// ---------------------------------------------------------------------------
// JAX threefry2x32 — exact replica of jax._src.prng threefry2x32 (20 rounds).
// ---------------------------------------------------------------------------
__device__ __forceinline__ uint32_t rotl32(uint32_t x, int r) {
  return (x << r) | (x >> (32 - r));
}

__device__ __forceinline__ void threefry2x32(uint32_t k0, uint32_t k1,
                                             uint32_t& x0, uint32_t& x1) {
  const uint32_t ks0 = k0, ks1 = k1, ks2 = k0 ^ k1 ^ 0x1BD11BDAu;
  x0 += ks0; x1 += ks1;
#define TF_R(r) { x0 += x1; x1 = rotl32(x1, r); x1 ^= x0; }
  TF_R(13) TF_R(15) TF_R(26) TF_R(6)
  x0 += ks1; x1 += ks2 + 1u;
  TF_R(17) TF_R(29) TF_R(16) TF_R(24)
  x0 += ks2; x1 += ks0 + 2u;
  TF_R(13) TF_R(15) TF_R(26) TF_R(6)
  x0 += ks0; x1 += ks1 + 3u;
  TF_R(17) TF_R(29) TF_R(16) TF_R(24)
  x0 += ks1; x1 += ks2 + 4u;
  TF_R(13) TF_R(15) TF_R(26) TF_R(6)
  x0 += ks2; x1 += ks0 + 5u;
#undef TF_R
}

// ---------------------------------------------------------------------------
// Phase B: softmax along k (256 elems) + deterministic dropout (key 42, p=0.9).
// PARTITIONABLE threefry (JAX >= 0.4.36 default):
//   counts = iota(uint64); bits[i] = out0 ^ out1 of hash(hi32(i), lo32(i)).
// For size < 2^32: bits[i] = out0 ^ out1 of threefry2x32(key, (0, i)).
// One block of 256 threads per (h,q) row.
// ---------------------------------------------------------------------------
__global__ __launch_bounds__(256) void softmax_dropout_kernel(float* __restrict__ attn) {
  const int row = blockIdx.x;      // h*256 + q
  const int k = threadIdx.x;       // 0..255
  const size_t base = (size_t)row * SS;

  float v = attn[base + k];

  __shared__ float red[256];
  red[k] = v;
  __syncthreads();
#pragma unroll
  for (int s = 128; s > 0; s >>= 1) {
    if (k < s) red[k] = fmaxf(red[k], red[k + s]);
    __syncthreads();
  }
  const float m = red[0];
  __syncthreads();

  const float e = expf(v - m);
  red[k] = e;
  __syncthreads();
#pragma unroll
  for (int s = 128; s > 0; s >>= 1) {
    if (k < s) red[k] += red[k + s];
    __syncthreads();
  }
  float p = e / red[0];

  // Exact JAX bernoulli(key(42), 0.1, (1,128,256,256)) with partitionable threefry.
  const uint32_t i = (uint32_t)row * (uint32_t)SS + (uint32_t)k;
  uint32_t x0 = 0u, x1 = i;        // (hi32, lo32) of uint64 counter i
  threefry2x32(0u, 42u, x0, x1);
  const uint32_t bits = x0 ^ x1;
  const float u = __uint_as_float((bits >> 9) | 0x3F800000u) - 1.0f;

  p = (u < 0.1f) ? (p / 0.1f) : 0.0f;
  attn[base + k] = p;
}

// ---------------------------------------------------------------------------
// Phase C: out[h,q,d] = sum_k P[h,q,k] * V[h,k,d].
// 64(q) x 64(d) tile per block, K-loop over S=256 in chunks of 16.
// ---------------------------------------------------------------------------
__global__ __launch_bounds__(256) void pv_kernel(
    const float* __restrict__ P, const float* __restrict__ V,
    float* __restrict__ out) {
  const int h  = blockIdx.z;
  const int q0 = blockIdx.y * TS;
  const int d0 = blockIdx.x * TS;
  const float* Ph = P + (size_t)h * SS * SS;
  const float* Vh = V + (size_t)h * SS * DD;

  __shared__ float As[KC][TS + 1];   // As[kk][q]
  __shared__ float Bs[KC][TS];       // Bs[kk][d]

  const int tid = threadIdx.x;
  const int tx = tid & 15;
  const int ty = tid >> 4;

  const int ar = tid >> 2;          // P row 0..63
  const int ac = (tid & 3) * 4;     // P k-offset 0,4,8,12
  const int br = tid >> 4;          // V row 0..15
  const int bc = (tid & 15) * 4;    // V d-offset

  float acc[4][4] = {};

  for (int kb = 0; kb < SS; kb += KC) {
    float4 a = *(const float4*)(Ph + (size_t)(q0 + ar) * SS + kb + ac);
    As[ac + 0][ar] = a.x; As[ac + 1][ar] = a.y; As[ac + 2][ar] = a.z; As[ac + 3][ar] = a.w;
    float4 b = *(const float4*)(Vh + (size_t)(kb + br) * DD + d0 + bc);
    *(float4*)&Bs[br][bc] = b;
    __syncthreads();
#pragma unroll
    for (int kk = 0; kk < KC; kk++) {
      float av[4], bv[4];
#pragma unroll
      for (int i = 0; i < 4; i++) { av[i] = As[kk][ty * 4 + i]; bv[i] = Bs[kk][tx * 4 + i]; }
#pragma unroll
      for (int i = 0; i < 4; i++)
#pragma unroll
        for (int j = 0; j < 4; j++) acc[i][j] += av[i] * bv[j];
    }
    __syncthreads();
  }

#pragma unroll
  for (int i = 0; i < 4; i++) {
    const int q = q0 + ty * 4 + i;
#pragma unroll
    for (int j = 0; j < 4; j++) {
      const int d = d0 + tx * 4 + j;
      out[((size_t)h * SS + q) * DD + d] = acc[i][j];
    }
  }
}

// ---------------------------------------------------------------------------
// Launch
// ---------------------------------------------------------------------------
extern "C" void kernel_launch(void* const* d_in, const int* in_sizes, int n_in,
                              void* d_out, int out_size) {
  const float* Q    = (const float*)d_in[0];
  const float* K    = (const float*)d_in[1];
  const float* V    = (const float*)d_in[2];
  const float* mask = (const float*)d_in[3];
  float* out = (float*)d_out;

  float* attn = nullptr;
  cudaGetSymbolAddress((void**)&attn, g_attn);

  // QK^T * scale + mask
  qk_kernel<<<dim3(SS / TS, SS / TS, HH), 256>>>(Q, K, mask, attn);
  // softmax + exact threefry dropout (partitionable layout)
  softmax_dropout_kernel<<<HH * SS, 256>>>(attn);
  // P @ V
  pv_kernel<<<dim3(DD / TS, SS / TS, HH), 256>>>(attn, V, out);
}

// round 5
// speedup vs baseline: 2.6386x; 2.6323x over previous
#include <cuda_runtime.h>
#include <cuda_bf16.h>
#include <cstdint>

// B=1, H=128, S=256, D=2048, fp32 in/out.
#define HH 128
#define SS 256
#define DD 2048

// ---------------------------------------------------------------------------
// Device scratch (no allocs allowed anywhere).
// ---------------------------------------------------------------------------
__device__ float          g_attn[(size_t)HH * SS * SS];   // fp32 scores
__device__ __nv_bfloat16  g_qhi[(size_t)HH * SS * DD];
__device__ __nv_bfloat16  g_qlo[(size_t)HH * SS * DD];
__device__ __nv_bfloat16  g_khi[(size_t)HH * SS * DD];
__device__ __nv_bfloat16  g_klo[(size_t)HH * SS * DD];
__device__ __nv_bfloat16  g_vthi[(size_t)HH * DD * SS];   // V^T [h,d,s]
__device__ __nv_bfloat16  g_vtlo[(size_t)HH * DD * SS];
__device__ __nv_bfloat16  g_phi[(size_t)HH * SS * SS];    // P hi [h,q,s]
__device__ __nv_bfloat16  g_plo[(size_t)HH * SS * SS];

// ---------------------------------------------------------------------------
// Helpers
// ---------------------------------------------------------------------------
__device__ __forceinline__ uint32_t smem_to_u32(const void* p) {
  uint32_t a;
  asm("{ .reg .u64 t; cvta.to.shared.u64 t, %1; cvt.u32.u64 %0, t; }" : "=r"(a) : "l"(p));
  return a;
}
#define SWZ(o) ((o) ^ (((o) >> 3) & 0x70))

__device__ __forceinline__ void cp_async16(uint32_t dst, const void* src) {
  asm volatile("cp.async.cg.shared.global [%0], [%1], 16;" :: "r"(dst), "l"(src) : "memory");
}
__device__ __forceinline__ void cp_commit() {
  asm volatile("cp.async.commit_group;" ::: "memory");
}
__device__ __forceinline__ void cp_wait0() {
  asm volatile("cp.async.wait_group 0;" ::: "memory");
}
__device__ __forceinline__ void cp_wait1() {
  asm volatile("cp.async.wait_group 1;" ::: "memory");
}

__device__ __forceinline__ void ldsm_x4(uint32_t addr, uint32_t* r) {
  asm volatile("ldmatrix.sync.aligned.m8n8.x4.shared.b16 {%0,%1,%2,%3}, [%4];"
               : "=r"(r[0]), "=r"(r[1]), "=r"(r[2]), "=r"(r[3]) : "r"(addr));
}

__device__ __forceinline__ void mma16816(float* c, const uint32_t* a, const uint32_t* b) {
  asm volatile(
      "mma.sync.aligned.m16n8k16.row.col.f32.bf16.bf16.f32 "
      "{%0,%1,%2,%3}, {%4,%5,%6,%7}, {%8,%9}, {%0,%1,%2,%3};"
      : "+f"(c[0]), "+f"(c[1]), "+f"(c[2]), "+f"(c[3])
      : "r"(a[0]), "r"(a[1]), "r"(a[2]), "r"(a[3]), "r"(b[0]), "r"(b[1]));
}

// SMEM tile layout: 128 rows x 128 bytes. Row r, k-chunk of 32 bf16:
//   bytes [0,64)  = hi plane (32 bf16), bytes [64,128) = lo plane.
// SW128 swizzled on 16B granularity. A at +0, B at +16384 per stage; stage stride 32768.
#define TILE_A 0
#define TILE_B 16384
#define STAGE_STRIDE 32768
#define SMEM_BYTES 65536

// A-fragment address: m16 tile at rows mt.., k-step ks (0/1), plane p.
__device__ __forceinline__ uint32_t a_frag_addr(uint32_t tb, int mt, int ks, int p, int lid) {
  uint32_t off = (uint32_t)(mt + (lid & 15)) * 128 + p * 64 + ks * 32 + ((lid >> 4) * 16);
  return tb + SWZ(off);
}
// B-fragment address: loads two n8 tiles (nt, nt+8) for k-step ks, plane p.
__device__ __forceinline__ uint32_t b_frag_addr(uint32_t tb, int nt, int ks, int p, int lid) {
  uint32_t off = (uint32_t)(nt + ((lid >> 4) & 1) * 8 + (lid & 7)) * 128
               + p * 64 + ks * 32 + (((lid >> 3) & 1) * 16);
  return tb + SWZ(off);
}

// ---------------------------------------------------------------------------
// Chunk loader: A tile rows [arow0..+128) x 32 k, B tile rows [brow0..+128) x 32 k,
// from hi/lo bf16 planes into stage buffer. 2048 16B segments, 8 per thread.
// ---------------------------------------------------------------------------
__device__ __forceinline__ void load_chunk(
    uint32_t sbase, int stage,
    const __nv_bfloat16* __restrict__ Ahi, const __nv_bfloat16* __restrict__ Alo,
    size_t arow0, size_t astride,
    const __nv_bfloat16* __restrict__ Bhi, const __nv_bfloat16* __restrict__ Blo,
    size_t brow0, size_t bstride, int kb, int tid) {
  const uint32_t stb = sbase + stage * STAGE_STRIDE;
#pragma unroll
  for (int it = 0; it < 8; it++) {
    int s = tid + it * 256;          // 0..2047
    int tile = s >> 10;              // 0=A, 1=B
    int w = s & 1023;
    int r = w >> 3;
    int q = w & 7;
    int p = q >> 2;                  // 0=hi, 1=lo
    int c16 = q & 3;
    const __nv_bfloat16* g;
    size_t row;
    size_t stride;
    if (tile == 0) { g = p ? Alo : Ahi; row = arow0 + r; stride = astride; }
    else           { g = p ? Blo : Bhi; row = brow0 + r; stride = bstride; }
    const void* src = g + row * stride + kb + c16 * 8;
    uint32_t off = (uint32_t)r * 128 + p * 64 + c16 * 16;
    cp_async16(stb + tile * 16384 + SWZ(off), src);
  }
  cp_commit();
}

// ---------------------------------------------------------------------------
// Compute one k-chunk (32) for this warp: 3-term hi/lo product into acc[2][8][4].
// ---------------------------------------------------------------------------
__device__ __forceinline__ void compute_chunk(
    uint32_t sbase, int stage, int warp_m, int warp_n, int lid, float acc[2][8][4]) {
  const uint32_t ta = sbase + stage * STAGE_STRIDE + TILE_A;
  const uint32_t tb = sbase + stage * STAGE_STRIDE + TILE_B;
  const int m0 = warp_m * 32;
  const int n0 = warp_n * 64;
#pragma unroll
  for (int ks = 0; ks < 2; ks++) {
    uint32_t ahi[2][4], alo[2][4], b[4][4];
#pragma unroll
    for (int mi = 0; mi < 2; mi++) {
      ldsm_x4(a_frag_addr(ta, m0 + mi * 16, ks, 0, lid), ahi[mi]);
      ldsm_x4(a_frag_addr(ta, m0 + mi * 16, ks, 1, lid), alo[mi]);
    }
    // B hi
#pragma unroll
    for (int nj = 0; nj < 4; nj++) ldsm_x4(b_frag_addr(tb, n0 + nj * 16, ks, 0, lid), b[nj]);
#pragma unroll
    for (int mi = 0; mi < 2; mi++)
#pragma unroll
      for (int ni = 0; ni < 8; ni++) {
        uint32_t bb[2] = { b[ni >> 1][(ni & 1) * 2], b[ni >> 1][(ni & 1) * 2 + 1] };
        mma16816(acc[mi][ni], ahi[mi], bb);   // hi*hi
      }
#pragma unroll
    for (int mi = 0; mi < 2; mi++)
#pragma unroll
      for (int ni = 0; ni < 8; ni++) {
        uint32_t bb[2] = { b[ni >> 1][(ni & 1) * 2], b[ni >> 1][(ni & 1) * 2 + 1] };
        mma16816(acc[mi][ni], alo[mi], bb);   // lo*hi
      }
    // B lo (reuse b regs)
#pragma unroll
    for (int nj = 0; nj < 4; nj++) ldsm_x4(b_frag_addr(tb, n0 + nj * 16, ks, 1, lid), b[nj]);
#pragma unroll
    for (int mi = 0; mi < 2; mi++)
#pragma unroll
      for (int ni = 0; ni < 8; ni++) {
        uint32_t bb[2] = { b[ni >> 1][(ni & 1) * 2], b[ni >> 1][(ni & 1) * 2 + 1] };
        mma16816(acc[mi][ni], ahi[mi], bb);   // hi*lo
      }
  }
}

// ---------------------------------------------------------------------------
// QK kernel: scores[h, q0+0..127, n0+0..127] = (Q.K^T)*scale + mask
// ---------------------------------------------------------------------------
__global__ __launch_bounds__(256, 2) void qk_mma_kernel(
    const __nv_bfloat16* __restrict__ Qhi, const __nv_bfloat16* __restrict__ Qlo,
    const __nv_bfloat16* __restrict__ Khi, const __nv_bfloat16* __restrict__ Klo,
    const float* __restrict__ mask, float* __restrict__ attn) {
  extern __shared__ char smem[];
  const uint32_t sbase = smem_to_u32(smem);
  const int tid = threadIdx.x, wid = tid >> 5, lid = tid & 31;
  const int warp_m = wid >> 1, warp_n = wid & 1;
  const int n0 = blockIdx.x * 128;     // k (seq) tile
  const int q0 = blockIdx.y * 128;     // q tile
  const int h = blockIdx.z;

  const size_t arow0 = (size_t)h * SS + q0;
  const size_t brow0 = (size_t)h * SS + n0;

  float acc[2][8][4];
#pragma unroll
  for (int mi = 0; mi < 2; mi++)
#pragma unroll
    for (int ni = 0; ni < 8; ni++)
#pragma unroll
      for (int j = 0; j < 4; j++) acc[mi][ni][j] = 0.0f;

  const int NCHUNK = DD / 32;  // 64
  load_chunk(sbase, 0, Qhi, Qlo, arow0, DD, Khi, Klo, brow0, DD, 0, tid);
  for (int ck = 0; ck < NCHUNK; ck++) {
    if (ck + 1 < NCHUNK) {
      load_chunk(sbase, (ck + 1) & 1, Qhi, Qlo, arow0, DD, Khi, Klo, brow0, DD,
                 (ck + 1) * 32, tid);
      cp_wait1();
    } else {
      cp_wait0();
    }
    __syncthreads();
    compute_chunk(sbase, ck & 1, warp_m, warp_n, lid, acc);
    __syncthreads();
  }

  // Epilogue: scale + mask, write fp32 scores.
  const float scale = 0.022097086912079608f;  // 1/sqrt(2048)
#pragma unroll
  for (int mi = 0; mi < 2; mi++) {
    const int r0 = q0 + warp_m * 32 + mi * 16 + (lid >> 2);
#pragma unroll
    for (int ni = 0; ni < 8; ni++) {
      const int c = n0 + warp_n * 64 + ni * 8 + (lid & 3) * 2;
#pragma unroll
      for (int half = 0; half < 2; half++) {
        const int r = r0 + half * 8;
        float v0 = acc[mi][ni][half * 2 + 0] * scale + mask[(size_t)r * SS + c];
        float v1 = acc[mi][ni][half * 2 + 1] * scale + mask[(size_t)r * SS + c + 1];
        *(float2*)(attn + ((size_t)h * SS + r) * SS + c) = make_float2(v0, v1);
      }
    }
  }
}

// ---------------------------------------------------------------------------
// PV kernel: out[h, q0+0..127, d0+0..127] = P @ V  (B operand = V^T planes)
// ---------------------------------------------------------------------------
__global__ __launch_bounds__(256, 2) void pv_mma_kernel(
    const __nv_bfloat16* __restrict__ Phi, const __nv_bfloat16* __restrict__ Plo,
    const __nv_bfloat16* __restrict__ Vthi, const __nv_bfloat16* __restrict__ Vtlo,
    float* __restrict__ out) {
  extern __shared__ char smem[];
  const uint32_t sbase = smem_to_u32(smem);
  const int tid = threadIdx.x, wid = tid >> 5, lid = tid & 31;
  const int warp_m = wid >> 1, warp_n = wid & 1;
  const int d0 = blockIdx.x * 128;
  const int q0 = blockIdx.y * 128;
  const int h = blockIdx.z;

  const size_t arow0 = (size_t)h * SS + q0;
  const size_t brow0 = (size_t)h * DD + d0;

  float acc[2][8][4];
#pragma unroll
  for (int mi = 0; mi < 2; mi++)
#pragma unroll
    for (int ni = 0; ni < 8; ni++)
#pragma unroll
      for (int j = 0; j < 4; j++) acc[mi][ni][j] = 0.0f;

  const int NCHUNK = SS / 32;  // 8
  load_chunk(sbase, 0, Phi, Plo, arow0, SS, Vthi, Vtlo, brow0, SS, 0, tid);
  for (int ck = 0; ck < NCHUNK; ck++) {
    if (ck + 1 < NCHUNK) {
      load_chunk(sbase, (ck + 1) & 1, Phi, Plo, arow0, SS, Vthi, Vtlo, brow0, SS,
                 (ck + 1) * 32, tid);
      cp_wait1();
    } else {
      cp_wait0();
    }
    __syncthreads();
    compute_chunk(sbase, ck & 1, warp_m, warp_n, lid, acc);
    __syncthreads();
  }

#pragma unroll
  for (int mi = 0; mi < 2; mi++) {
    const int r0 = q0 + warp_m * 32 + mi * 16 + (lid >> 2);
#pragma unroll
    for (int ni = 0; ni < 8; ni++) {
      const int c = d0 + warp_n * 64 + ni * 8 + (lid & 3) * 2;
#pragma unroll
      for (int half = 0; half < 2; half++) {
        const int r = r0 + half * 8;
        *(float2*)(out + ((size_t)h * SS + r) * DD + c) =
            make_float2(acc[mi][ni][half * 2 + 0], acc[mi][ni][half * 2 + 1]);
      }
    }
  }
}

// ---------------------------------------------------------------------------
// fp32 -> bf16 hi/lo split
// ---------------------------------------------------------------------------
__device__ __forceinline__ void split_bf16(float x, __nv_bfloat16& hi, __nv_bfloat16& lo) {
  hi = __float2bfloat16(x);
  lo = __float2bfloat16(x - __bfloat162float(hi));
}

__global__ __launch_bounds__(256) void split_kernel(
    const float* __restrict__ src, __nv_bfloat16* __restrict__ hi,
    __nv_bfloat16* __restrict__ lo, size_t n4) {
  size_t i = (size_t)blockIdx.x * blockDim.x + threadIdx.x;
  if (i >= n4) return;
  float4 x = ((const float4*)src)[i];
  __nv_bfloat16 h0, h1, h2, h3, l0, l1, l2, l3;
  split_bf16(x.x, h0, l0); split_bf16(x.y, h1, l1);
  split_bf16(x.z, h2, l2); split_bf16(x.w, h3, l3);
  __nv_bfloat162* hp = (__nv_bfloat162*)(hi + i * 4);
  __nv_bfloat162* lp = (__nv_bfloat162*)(lo + i * 4);
  hp[0] = __nv_bfloat162(h0, h1); hp[1] = __nv_bfloat162(h2, h3);
  lp[0] = __nv_bfloat162(l0, l1); lp[1] = __nv_bfloat162(l2, l3);
}

// Transpose-split V: V[h,s,d] fp32 -> Vt hi/lo [h,d,s] bf16.
__global__ __launch_bounds__(256) void vtrans_kernel(
    const float* __restrict__ V, __nv_bfloat16* __restrict__ vthi,
    __nv_bfloat16* __restrict__ vtlo) {
  const int h = blockIdx.z;
  const int d0 = blockIdx.x * 32;
  const int s0 = blockIdx.y * 32;
  __shared__ float t[32][33];
  const int tx = threadIdx.x, ty = threadIdx.y;  // 32 x 8
#pragma unroll
  for (int i = 0; i < 4; i++) {
    int s = s0 + ty + i * 8;
    t[ty + i * 8][tx] = V[((size_t)h * SS + s) * DD + d0 + tx];
  }
  __syncthreads();
#pragma unroll
  for (int i = 0; i < 4; i++) {
    int d = d0 + ty + i * 8;
    int s = s0 + tx;
    __nv_bfloat16 hi, lo;
    split_bf16(t[tx][ty + i * 8], hi, lo);
    size_t o = ((size_t)h * DD + d) * SS + s;
    vthi[o] = hi; vtlo[o] = lo;
  }
}

// ---------------------------------------------------------------------------
// JAX threefry2x32 (20 rounds) — exact.
// ---------------------------------------------------------------------------
__device__ __forceinline__ uint32_t rotl32(uint32_t x, int r) {
  return (x << r) | (x >> (32 - r));
}
__device__ __forceinline__ void threefry2x32(uint32_t k0, uint32_t k1,
                                             uint32_t& x0, uint32_t& x1) {
  const uint32_t ks0 = k0, ks1 = k1, ks2 = k0 ^ k1 ^ 0x1BD11BDAu;
  x0 += ks0; x1 += ks1;
#define TF_R(r) { x0 += x1; x1 = rotl32(x1, r); x1 ^= x0; }
  TF_R(13) TF_R(15) TF_R(26) TF_R(6)
  x0 += ks1; x1 += ks2 + 1u;
  TF_R(17) TF_R(29) TF_R(16) TF_R(24)
  x0 += ks2; x1 += ks0 + 2u;
  TF_R(13) TF_R(15) TF_R(26) TF_R(6)
  x0 += ks0; x1 += ks1 + 3u;
  TF_R(17) TF_R(29) TF_R(16) TF_R(24)
  x0 += ks1; x1 += ks2 + 4u;
  TF_R(13) TF_R(15) TF_R(26) TF_R(6)
  x0 += ks2; x1 += ks0 + 5u;
#undef TF_R
}

// ---------------------------------------------------------------------------
// Softmax + dropout (partitionable threefry, key 42, p=0.9) -> P hi/lo bf16.
// ---------------------------------------------------------------------------
__global__ __launch_bounds__(256) void softmax_dropout_kernel(
    const float* __restrict__ attn, __nv_bfloat16* __restrict__ phi,
    __nv_bfloat16* __restrict__ plo) {
  const int row = blockIdx.x;  // h*256 + q
  const int k = threadIdx.x;
  const size_t base = (size_t)row * SS;

  float v = attn[base + k];

  __shared__ float red[256];
  red[k] = v;
  __syncthreads();
#pragma unroll
  for (int s = 128; s > 0; s >>= 1) {
    if (k < s) red[k] = fmaxf(red[k], red[k + s]);
    __syncthreads();
  }
  const float m = red[0];
  __syncthreads();
  const float e = expf(v - m);
  red[k] = e;
  __syncthreads();
#pragma unroll
  for (int s = 128; s > 0; s >>= 1) {
    if (k < s) red[k] += red[k + s];
    __syncthreads();
  }
  float p = e / red[0];

  const uint32_t i = (uint32_t)row * (uint32_t)SS + (uint32_t)k;
  uint32_t x0 = 0u, x1 = i;
  threefry2x32(0u, 42u, x0, x1);
  const uint32_t bits = x0 ^ x1;
  const float u = __uint_as_float((bits >> 9) | 0x3F800000u) - 1.0f;
  p = (u < 0.1f) ? (p / 0.1f) : 0.0f;

  __nv_bfloat16 hi, lo;
  split_bf16(p, hi, lo);
  phi[base + k] = hi;
  plo[base + k] = lo;
}

// ---------------------------------------------------------------------------
// Launch
// ---------------------------------------------------------------------------
extern "C" void kernel_launch(void* const* d_in, const int* in_sizes, int n_in,
                              void* d_out, int out_size) {
  const float* Q = (const float*)d_in[0];
  const float* K = (const float*)d_in[1];
  const float* V = (const float*)d_in[2];
  const float* mask = (const float*)d_in[3];
  float* out = (float*)d_out;

  float* attn; __nv_bfloat16 *qhi, *qlo, *khi, *klo, *vthi, *vtlo, *phi, *plo;
  cudaGetSymbolAddress((void**)&attn, g_attn);
  cudaGetSymbolAddress((void**)&qhi, g_qhi);
  cudaGetSymbolAddress((void**)&qlo, g_qlo);
  cudaGetSymbolAddress((void**)&khi, g_khi);
  cudaGetSymbolAddress((void**)&klo, g_klo);
  cudaGetSymbolAddress((void**)&vthi, g_vthi);
  cudaGetSymbolAddress((void**)&vtlo, g_vtlo);
  cudaGetSymbolAddress((void**)&phi, g_phi);
  cudaGetSymbolAddress((void**)&plo, g_plo);

  cudaFuncSetAttribute(qk_mma_kernel, cudaFuncAttributeMaxDynamicSharedMemorySize, SMEM_BYTES);
  cudaFuncSetAttribute(pv_mma_kernel, cudaFuncAttributeMaxDynamicSharedMemorySize, SMEM_BYTES);

  const size_t n = (size_t)HH * SS * DD;  // 67,108,864
  const size_t n4 = n / 4;
  split_kernel<<<(unsigned)(n4 / 256), 256>>>(Q, qhi, qlo, n4);
  split_kernel<<<(unsigned)(n4 / 256), 256>>>(K, khi, klo, n4);
  vtrans_kernel<<<dim3(DD / 32, SS / 32, HH), dim3(32, 8)>>>(V, vthi, vtlo);

  // QK^T * scale + mask : block tile 128x128, grid (ktile, qtile, h)
  qk_mma_kernel<<<dim3(2, 2, HH), 256, SMEM_BYTES>>>(qhi, qlo, khi, klo, mask, attn);
  // softmax + exact threefry dropout -> P hi/lo planes
  softmax_dropout_kernel<<<HH * SS, 256>>>(attn, phi, plo);
  // P @ V : grid (dtile, qtile, h)
  pv_mma_kernel<<<dim3(DD / 128, 2, HH), 256, SMEM_BYTES>>>(phi, plo, vthi, vtlo, out);
}

// round 6
// speedup vs baseline: 2.6560x; 1.0066x over previous
#include <cuda_runtime.h>
#include <cuda_bf16.h>
#include <cstdint>

// B=1, H=128, S=256, D=2048, fp32 in/out.
#define HH 128
#define SS 256
#define DD 2048

// ---------------------------------------------------------------------------
// Device scratch (no allocs allowed anywhere).
// ---------------------------------------------------------------------------
__device__ __nv_bfloat16  g_vthi[(size_t)HH * DD * SS];   // V^T [h,d,s]
__device__ __nv_bfloat16  g_vtlo[(size_t)HH * DD * SS];
__device__ __nv_bfloat16  g_phi[(size_t)HH * SS * SS];    // P hi [h,q,s]
__device__ __nv_bfloat16  g_plo[(size_t)HH * SS * SS];

// ---------------------------------------------------------------------------
// Helpers
// ---------------------------------------------------------------------------
__device__ __forceinline__ uint32_t smem_to_u32(const void* p) {
  uint32_t a;
  asm("{ .reg .u64 t; cvta.to.shared.u64 t, %1; cvt.u32.u64 %0, t; }" : "=r"(a) : "l"(p));
  return a;
}
#define SWZ(o) ((o) ^ (((o) >> 3) & 0x70))

__device__ __forceinline__ void cp_async16(uint32_t dst, const void* src) {
  asm volatile("cp.async.cg.shared.global [%0], [%1], 16;" :: "r"(dst), "l"(src) : "memory");
}
__device__ __forceinline__ void cp_commit() {
  asm volatile("cp.async.commit_group;" ::: "memory");
}
__device__ __forceinline__ void cp_wait0() {
  asm volatile("cp.async.wait_group 0;" ::: "memory");
}
__device__ __forceinline__ void cp_wait1() {
  asm volatile("cp.async.wait_group 1;" ::: "memory");
}

__device__ __forceinline__ void ldsm_x4(uint32_t addr, uint32_t* r) {
  asm volatile("ldmatrix.sync.aligned.m8n8.x4.shared.b16 {%0,%1,%2,%3}, [%4];"
               : "=r"(r[0]), "=r"(r[1]), "=r"(r[2]), "=r"(r[3]) : "r"(addr));
}

__device__ __forceinline__ void mma16816(float* c, const uint32_t* a, const uint32_t* b) {
  asm volatile(
      "mma.sync.aligned.m16n8k16.row.col.f32.bf16.bf16.f32 "
      "{%0,%1,%2,%3}, {%4,%5,%6,%7}, {%8,%9}, {%0,%1,%2,%3};"
      : "+f"(c[0]), "+f"(c[1]), "+f"(c[2]), "+f"(c[3])
      : "r"(a[0]), "r"(a[1]), "r"(a[2]), "r"(a[3]), "r"(b[0]), "r"(b[1]));
}

__device__ __forceinline__ void split_bf16(float x, __nv_bfloat16& hi, __nv_bfloat16& lo) {
  hi = __float2bfloat16(x);
  lo = __float2bfloat16(x - __bfloat162float(hi));
}

// SMEM row format (both kernels): 128 bytes per logical row, k-chunk of 32 bf16:
//   bytes [0,64) = hi plane (32 bf16), bytes [64,128) = lo plane, SW128 swizzled.

// A-fragment address: m16 tile at rows mt.., k-step ks (0/1), plane p.
__device__ __forceinline__ uint32_t a_frag_addr(uint32_t tb, int mt, int ks, int p, int lid) {
  uint32_t off = (uint32_t)(mt + (lid & 15)) * 128 + p * 64 + ks * 32 + ((lid >> 4) * 16);
  return tb + SWZ(off);
}
// B-fragment address: loads two n8 tiles (nt, nt+8) for k-step ks, plane p.
__device__ __forceinline__ uint32_t b_frag_addr(uint32_t tb, int nt, int ks, int p, int lid) {
  uint32_t off = (uint32_t)(nt + ((lid >> 4) & 1) * 8 + (lid & 7)) * 128
               + p * 64 + ks * 32 + (((lid >> 3) & 1) * 16);
  return tb + SWZ(off);
}

// ---------------------------------------------------------------------------
// Shared compute core: one k-chunk (32), 3-term hi/lo product, warp tile 32x64.
// ta/tb = smem base addrs of A/B tiles for this stage.
// ---------------------------------------------------------------------------
__device__ __forceinline__ void compute_chunk(
    uint32_t ta, uint32_t tb, int m0, int n0, int lid, float acc[2][8][4]) {
#pragma unroll
  for (int ks = 0; ks < 2; ks++) {
    uint32_t ahi[2][4], alo[2][4], b[4][4];
#pragma unroll
    for (int mi = 0; mi < 2; mi++) {
      ldsm_x4(a_frag_addr(ta, m0 + mi * 16, ks, 0, lid), ahi[mi]);
      ldsm_x4(a_frag_addr(ta, m0 + mi * 16, ks, 1, lid), alo[mi]);
    }
#pragma unroll
    for (int nj = 0; nj < 4; nj++) ldsm_x4(b_frag_addr(tb, n0 + nj * 16, ks, 0, lid), b[nj]);
#pragma unroll
    for (int mi = 0; mi < 2; mi++)
#pragma unroll
      for (int ni = 0; ni < 8; ni++) {
        uint32_t bb[2] = { b[ni >> 1][(ni & 1) * 2], b[ni >> 1][(ni & 1) * 2 + 1] };
        mma16816(acc[mi][ni], ahi[mi], bb);   // hi*hi
      }
#pragma unroll
    for (int mi = 0; mi < 2; mi++)
#pragma unroll
      for (int ni = 0; ni < 8; ni++) {
        uint32_t bb[2] = { b[ni >> 1][(ni & 1) * 2], b[ni >> 1][(ni & 1) * 2 + 1] };
        mma16816(acc[mi][ni], alo[mi], bb);   // lo*hi
      }
#pragma unroll
    for (int nj = 0; nj < 4; nj++) ldsm_x4(b_frag_addr(tb, n0 + nj * 16, ks, 1, lid), b[nj]);
#pragma unroll
    for (int mi = 0; mi < 2; mi++)
#pragma unroll
      for (int ni = 0; ni < 8; ni++) {
        uint32_t bb[2] = { b[ni >> 1][(ni & 1) * 2], b[ni >> 1][(ni & 1) * 2 + 1] };
        mma16816(acc[mi][ni], ahi[mi], bb);   // hi*lo
      }
  }
}

// ---------------------------------------------------------------------------
// JAX threefry2x32 (20 rounds) — exact.
// ---------------------------------------------------------------------------
__device__ __forceinline__ uint32_t rotl32(uint32_t x, int r) {
  return (x << r) | (x >> (32 - r));
}
__device__ __forceinline__ void threefry2x32(uint32_t k0, uint32_t k1,
                                             uint32_t& x0, uint32_t& x1) {
  const uint32_t ks0 = k0, ks1 = k1, ks2 = k0 ^ k1 ^ 0x1BD11BDAu;
  x0 += ks0; x1 += ks1;
#define TF_R(r) { x0 += x1; x1 = rotl32(x1, r); x1 ^= x0; }
  TF_R(13) TF_R(15) TF_R(26) TF_R(6)
  x0 += ks1; x1 += ks2 + 1u;
  TF_R(17) TF_R(29) TF_R(16) TF_R(24)
  x0 += ks2; x1 += ks0 + 2u;
  TF_R(13) TF_R(15) TF_R(26) TF_R(6)
  x0 += ks0; x1 += ks1 + 3u;
  TF_R(17) TF_R(29) TF_R(16) TF_R(24)
  x0 += ks1; x1 += ks2 + 4u;
  TF_R(13) TF_R(15) TF_R(26) TF_R(6)
  x0 += ks2; x1 += ks0 + 5u;
#undef TF_R
}
// keep-prob draw for flat index i (partitionable layout, key (0,42)).
__device__ __forceinline__ bool keep_draw(uint32_t i) {
  uint32_t x0 = 0u, x1 = i;
  threefry2x32(0u, 42u, x0, x1);
  const uint32_t bits = x0 ^ x1;
  const float u = __uint_as_float((bits >> 9) | 0x3F800000u) - 1.0f;
  return u < 0.1f;
}

// ===========================================================================
// Fused QK + softmax + dropout kernel.
// Grid (2, HH), 512 threads. Block tile: 128 q-rows x 256 k-cols (full row).
// Reads Q,K fp32 directly; on-the-fly hi/lo split into SW128 smem; double-
// buffered; epilogue: scale+mask, row softmax, threefry dropout, P hi/lo out.
// ===========================================================================
#define QKS_STAGE 49152            // A 128x128B (16KB) + B 256x128B (32KB)
#define QKS_SMEM  (2 * QKS_STAGE)  // 96KB

__device__ __forceinline__ void qks_ldg(
    float4* buf, const float* __restrict__ Qf, const float* __restrict__ Kf,
    size_t qrow0, size_t krow0, int kb, int tid) {
#pragma unroll
  for (int i = 0; i < 6; i++) {
    const int seg = tid + i * 512;                // 0..3071 (1024 A + 2048 B)
    const int tile = (i >= 2) ? 1 : 0;            // i 0,1 -> A, else B
    const int w = seg - tile * 1024;
    const int r = w >> 3, c4 = w & 7;
    const float* g = tile ? (Kf + (krow0 + r) * DD) : (Qf + (qrow0 + r) * DD);
    buf[i] = *(const float4*)(g + kb + c4 * 4);
  }
}

__device__ __forceinline__ void qks_sts(uint32_t stb, const float4* buf, int tid) {
#pragma unroll
  for (int i = 0; i < 6; i++) {
    const int seg = tid + i * 512;
    const int tile = (i >= 2) ? 1 : 0;
    const int w = seg - tile * 1024;
    const int r = w >> 3, c4 = w & 7;
    float4 v = buf[i];
    __nv_bfloat16 h0, h1, h2, h3, l0, l1, l2, l3;
    split_bf16(v.x, h0, l0); split_bf16(v.y, h1, l1);
    split_bf16(v.z, h2, l2); split_bf16(v.w, h3, l3);
    const uint32_t tbase = stb + tile * 16384;
    const uint32_t ohi = (uint32_t)r * 128 + c4 * 8;
    __nv_bfloat162 hp[2] = { __nv_bfloat162(h0, h1), __nv_bfloat162(h2, h3) };
    __nv_bfloat162 lp[2] = { __nv_bfloat162(l0, l1), __nv_bfloat162(l2, l3) };
    *(uint2*)(uintptr_t)0;  // (placeholder removed below)
    // hi plane
    asm volatile("st.shared.v2.b32 [%0], {%1, %2};" ::
                 "r"(tbase + SWZ(ohi)),
                 "r"(*(uint32_t*)&hp[0]), "r"(*(uint32_t*)&hp[1]) : "memory");
    // lo plane
    asm volatile("st.shared.v2.b32 [%0], {%1, %2};" ::
                 "r"(tbase + SWZ(ohi + 64)),
                 "r"(*(uint32_t*)&lp[0]), "r"(*(uint32_t*)&lp[1]) : "memory");
  }
}

__global__ __launch_bounds__(512, 1) void qks_kernel(
    const float* __restrict__ Qf, const float* __restrict__ Kf,
    const float* __restrict__ mask,
    __nv_bfloat16* __restrict__ phi, __nv_bfloat16* __restrict__ plo) {
  extern __shared__ char smem[];
  const uint32_t sbase = smem_to_u32(smem);
  const int tid = threadIdx.x, wid = tid >> 5, lid = tid & 31;
  const int warp_m = wid >> 2, warp_n = wid & 3;
  const int m0 = warp_m * 32, n0 = warp_n * 64;
  const int q0 = blockIdx.x * 128;
  const int h = blockIdx.y;

  const size_t qrow0 = (size_t)h * SS + q0;
  const size_t krow0 = (size_t)h * SS;

  float acc[2][8][4];
#pragma unroll
  for (int mi = 0; mi < 2; mi++)
#pragma unroll
    for (int ni = 0; ni < 8; ni++)
#pragma unroll
      for (int j = 0; j < 4; j++) acc[mi][ni][j] = 0.0f;

  float4 buf[6];
  const int NCHUNK = DD / 32;  // 64

  qks_ldg(buf, Qf, Kf, qrow0, krow0, 0, tid);
  qks_sts(sbase, buf, tid);
  for (int ck = 0; ck < NCHUNK; ck++) {
    if (ck + 1 < NCHUNK) qks_ldg(buf, Qf, Kf, qrow0, krow0, (ck + 1) * 32, tid);
    __syncthreads();
    const uint32_t stb = sbase + (ck & 1) * QKS_STAGE;
    compute_chunk(stb, stb + 16384, m0, n0, lid, acc);
    __syncthreads();
    if (ck + 1 < NCHUNK) qks_sts(sbase + ((ck + 1) & 1) * QKS_STAGE, buf, tid);
  }
  __syncthreads();

  // ---- epilogue: scale + mask ----
  const float scale = 0.022097086912079608f;  // 1/sqrt(2048)
  const int rr = lid >> 2, cc = lid & 3;
#pragma unroll
  for (int mi = 0; mi < 2; mi++)
#pragma unroll
    for (int ni = 0; ni < 8; ni++)
#pragma unroll
      for (int j = 0; j < 4; j++) {
        const int r = q0 + m0 + mi * 16 + (j >> 1) * 8 + rr;
        const int c = n0 + ni * 8 + cc * 2 + (j & 1);
        acc[mi][ni][j] = acc[mi][ni][j] * scale + mask[(size_t)r * SS + c];
      }

  // ---- row softmax across 4 n-warps ----
  float* sred = (float*)smem;  // [128 rows][4 warp_n]
  float rmax[2][2], rsum[2][2];
#pragma unroll
  for (int mi = 0; mi < 2; mi++)
#pragma unroll
    for (int hf = 0; hf < 2; hf++) {
      float m = -3.4e38f;
#pragma unroll
      for (int ni = 0; ni < 8; ni++) {
        m = fmaxf(m, acc[mi][ni][hf * 2 + 0]);
        m = fmaxf(m, acc[mi][ni][hf * 2 + 1]);
      }
      m = fmaxf(m, __shfl_xor_sync(0xffffffffu, m, 1));
      m = fmaxf(m, __shfl_xor_sync(0xffffffffu, m, 2));
      if (cc == 0) sred[(m0 + mi * 16 + hf * 8 + rr) * 4 + warp_n] = m;
      rmax[mi][hf] = m;
    }
  __syncthreads();
#pragma unroll
  for (int mi = 0; mi < 2; mi++)
#pragma unroll
    for (int hf = 0; hf < 2; hf++) {
      const int row = m0 + mi * 16 + hf * 8 + rr;
      float m = fmaxf(fmaxf(sred[row * 4 + 0], sred[row * 4 + 1]),
                      fmaxf(sred[row * 4 + 2], sred[row * 4 + 3]));
      rmax[mi][hf] = m;
    }
  __syncthreads();
#pragma unroll
  for (int mi = 0; mi < 2; mi++)
#pragma unroll
    for (int hf = 0; hf < 2; hf++) {
      float s = 0.0f;
#pragma unroll
      for (int ni = 0; ni < 8; ni++) {
        float e0 = expf(acc[mi][ni][hf * 2 + 0] - rmax[mi][hf]);
        float e1 = expf(acc[mi][ni][hf * 2 + 1] - rmax[mi][hf]);
        acc[mi][ni][hf * 2 + 0] = e0;
        acc[mi][ni][hf * 2 + 1] = e1;
        s += e0 + e1;
      }
      s += __shfl_xor_sync(0xffffffffu, s, 1);
      s += __shfl_xor_sync(0xffffffffu, s, 2);
      if (cc == 0) sred[(m0 + mi * 16 + hf * 8 + rr) * 4 + warp_n] = s;
      rsum[mi][hf] = s;
    }
  __syncthreads();
#pragma unroll
  for (int mi = 0; mi < 2; mi++)
#pragma unroll
    for (int hf = 0; hf < 2; hf++) {
      const int row = m0 + mi * 16 + hf * 8 + rr;
      rsum[mi][hf] = sred[row * 4 + 0] + sred[row * 4 + 1] +
                     sred[row * 4 + 2] + sred[row * 4 + 3];
    }

  // ---- dropout + split + store P planes ----
#pragma unroll
  for (int mi = 0; mi < 2; mi++)
#pragma unroll
    for (int hf = 0; hf < 2; hf++) {
      const int r = q0 + m0 + mi * 16 + hf * 8 + rr;       // global q
      const float inv = 1.0f / rsum[mi][hf];
      const uint32_t ibase = ((uint32_t)h * SS + (uint32_t)r) * SS;
#pragma unroll
      for (int ni = 0; ni < 8; ni++) {
        const int c = n0 + ni * 8 + cc * 2;
        float p0 = acc[mi][ni][hf * 2 + 0] * inv;
        float p1 = acc[mi][ni][hf * 2 + 1] * inv;
        p0 = keep_draw(ibase + c)     ? (p0 / 0.1f) : 0.0f;
        p1 = keep_draw(ibase + c + 1) ? (p1 / 0.1f) : 0.0f;
        __nv_bfloat16 h0, h1, l0, l1;
        split_bf16(p0, h0, l0); split_bf16(p1, h1, l1);
        const size_t o = ((size_t)h * SS + r) * SS + c;
        *(__nv_bfloat162*)(phi + o) = __nv_bfloat162(h0, h1);
        *(__nv_bfloat162*)(plo + o) = __nv_bfloat162(l0, l1);
      }
    }
}

// ===========================================================================
// PV kernel (unchanged from r5): out[h, q0..+128, d0..+128] = P @ V
// ===========================================================================
#define TILE_B 16384
#define STAGE_STRIDE 32768
#define SMEM_BYTES 65536

__device__ __forceinline__ void load_chunk(
    uint32_t sbase, int stage,
    const __nv_bfloat16* __restrict__ Ahi, const __nv_bfloat16* __restrict__ Alo,
    size_t arow0, size_t astride,
    const __nv_bfloat16* __restrict__ Bhi, const __nv_bfloat16* __restrict__ Blo,
    size_t brow0, size_t bstride, int kb, int tid) {
  const uint32_t stb = sbase + stage * STAGE_STRIDE;
#pragma unroll
  for (int it = 0; it < 8; it++) {
    int s = tid + it * 256;          // 0..2047
    int tile = s >> 10;              // 0=A, 1=B
    int w = s & 1023;
    int r = w >> 3;
    int q = w & 7;
    int p = q >> 2;                  // 0=hi, 1=lo
    int c16 = q & 3;
    const __nv_bfloat16* g;
    size_t row, stride;
    if (tile == 0) { g = p ? Alo : Ahi; row = arow0 + r; stride = astride; }
    else           { g = p ? Blo : Bhi; row = brow0 + r; stride = bstride; }
    const void* src = g + row * stride + kb + c16 * 8;
    uint32_t off = (uint32_t)r * 128 + p * 64 + c16 * 16;
    cp_async16(stb + tile * 16384 + SWZ(off), src);
  }
  cp_commit();
}

__global__ __launch_bounds__(256, 2) void pv_mma_kernel(
    const __nv_bfloat16* __restrict__ Phi, const __nv_bfloat16* __restrict__ Plo,
    const __nv_bfloat16* __restrict__ Vthi, const __nv_bfloat16* __restrict__ Vtlo,
    float* __restrict__ out) {
  extern __shared__ char smem[];
  const uint32_t sbase = smem_to_u32(smem);
  const int tid = threadIdx.x, wid = tid >> 5, lid = tid & 31;
  const int warp_m = wid >> 1, warp_n = wid & 1;
  const int d0 = blockIdx.x * 128;
  const int q0 = blockIdx.y * 128;
  const int h = blockIdx.z;

  const size_t arow0 = (size_t)h * SS + q0;
  const size_t brow0 = (size_t)h * DD + d0;

  float acc[2][8][4];
#pragma unroll
  for (int mi = 0; mi < 2; mi++)
#pragma unroll
    for (int ni = 0; ni < 8; ni++)
#pragma unroll
      for (int j = 0; j < 4; j++) acc[mi][ni][j] = 0.0f;

  const int NCHUNK = SS / 32;  // 8
  load_chunk(sbase, 0, Phi, Plo, arow0, SS, Vthi, Vtlo, brow0, SS, 0, tid);
  for (int ck = 0; ck < NCHUNK; ck++) {
    if (ck + 1 < NCHUNK) {
      load_chunk(sbase, (ck + 1) & 1, Phi, Plo, arow0, SS, Vthi, Vtlo, brow0, SS,
                 (ck + 1) * 32, tid);
      cp_wait1();
    } else {
      cp_wait0();
    }
    __syncthreads();
    const uint32_t stb = sbase + (ck & 1) * STAGE_STRIDE;
    compute_chunk(stb, stb + TILE_B, warp_m * 32, warp_n * 64, lid, acc);
    __syncthreads();
  }

#pragma unroll
  for (int mi = 0; mi < 2; mi++) {
    const int r0 = q0 + warp_m * 32 + mi * 16 + (lid >> 2);
#pragma unroll
    for (int ni = 0; ni < 8; ni++) {
      const int c = d0 + warp_n * 64 + ni * 8 + (lid & 3) * 2;
#pragma unroll
      for (int half = 0; half < 2; half++) {
        const int r = r0 + half * 8;
        *(float2*)(out + ((size_t)h * SS + r) * DD + c) =
            make_float2(acc[mi][ni][half * 2 + 0], acc[mi][ni][half * 2 + 1]);
      }
    }
  }
}

// ---------------------------------------------------------------------------
// Transpose-split V: V[h,s,d] fp32 -> Vt hi/lo [h,d,s] bf16.
// ---------------------------------------------------------------------------
__global__ __launch_bounds__(256) void vtrans_kernel(
    const float* __restrict__ V, __nv_bfloat16* __restrict__ vthi,
    __nv_bfloat16* __restrict__ vtlo) {
  const int h = blockIdx.z;
  const int d0 = blockIdx.x * 32;
  const int s0 = blockIdx.y * 32;
  __shared__ float t[32][33];
  const int tx = threadIdx.x, ty = threadIdx.y;  // 32 x 8
#pragma unroll
  for (int i = 0; i < 4; i++) {
    int s = s0 + ty + i * 8;
    t[ty + i * 8][tx] = V[((size_t)h * SS + s) * DD + d0 + tx];
  }
  __syncthreads();
#pragma unroll
  for (int i = 0; i < 4; i++) {
    int d = d0 + ty + i * 8;
    int s = s0 + tx;
    __nv_bfloat16 hi, lo;
    split_bf16(t[tx][ty + i * 8], hi, lo);
    size_t o = ((size_t)h * DD + d) * SS + s;
    vthi[o] = hi; vtlo[o] = lo;
  }
}

// ---------------------------------------------------------------------------
// Launch
// ---------------------------------------------------------------------------
extern "C" void kernel_launch(void* const* d_in, const int* in_sizes, int n_in,
                              void* d_out, int out_size) {
  const float* Q = (const float*)d_in[0];
  const float* K = (const float*)d_in[1];
  const float* V = (const float*)d_in[2];
  const float* mask = (const float*)d_in[3];
  float* out = (float*)d_out;

  __nv_bfloat16 *vthi, *vtlo, *phi, *plo;
  cudaGetSymbolAddress((void**)&vthi, g_vthi);
  cudaGetSymbolAddress((void**)&vtlo, g_vtlo);
  cudaGetSymbolAddress((void**)&phi, g_phi);
  cudaGetSymbolAddress((void**)&plo, g_plo);

  cudaFuncSetAttribute(qks_kernel, cudaFuncAttributeMaxDynamicSharedMemorySize, QKS_SMEM);
  cudaFuncSetAttribute(pv_mma_kernel, cudaFuncAttributeMaxDynamicSharedMemorySize, SMEM_BYTES);

  // V transpose+split (independent of qks; runs first on the same stream)
  vtrans_kernel<<<dim3(DD / 32, SS / 32, HH), dim3(32, 8)>>>(V, vthi, vtlo);
  // Fused QK^T -> scale+mask -> softmax -> dropout -> P hi/lo
  qks_kernel<<<dim3(2, HH), 512, QKS_SMEM>>>(Q, K, mask, phi, plo);
  // P @ V
  pv_mma_kernel<<<dim3(DD / 128, 2, HH), 256, SMEM_BYTES>>>(phi, plo, vthi, vtlo, out);
}

// round 7
// speedup vs baseline: 3.4555x; 1.3010x over previous
#include <cuda_runtime.h>
#include <cuda_bf16.h>
#include <cstdint>

// B=1, H=128, S=256, D=2048, fp32 in/out.
#define HH 128
#define SS 256
#define DD 2048

// ---------------------------------------------------------------------------
// Device scratch (no allocs allowed anywhere).
// ---------------------------------------------------------------------------
__device__ __nv_bfloat16  g_phi[(size_t)HH * SS * SS];    // P hi [h,q,s]
__device__ __nv_bfloat16  g_plo[(size_t)HH * SS * SS];

// ---------------------------------------------------------------------------
// Helpers
// ---------------------------------------------------------------------------
__device__ __forceinline__ uint32_t smem_to_u32(const void* p) {
  uint32_t a;
  asm("{ .reg .u64 t; cvta.to.shared.u64 t, %1; cvt.u32.u64 %0, t; }" : "=r"(a) : "l"(p));
  return a;
}
#define SWZ(o) ((o) ^ (((o) >> 3) & 0x70))

__device__ __forceinline__ void cp_async16(uint32_t dst, const void* src) {
  asm volatile("cp.async.cg.shared.global [%0], [%1], 16;" :: "r"(dst), "l"(src) : "memory");
}
__device__ __forceinline__ void cp_commit() {
  asm volatile("cp.async.commit_group;" ::: "memory");
}
__device__ __forceinline__ void cp_wait0() {
  asm volatile("cp.async.wait_group 0;" ::: "memory");
}
__device__ __forceinline__ void cp_wait1() {
  asm volatile("cp.async.wait_group 1;" ::: "memory");
}

__device__ __forceinline__ void ldsm_x4(uint32_t addr, uint32_t* r) {
  asm volatile("ldmatrix.sync.aligned.m8n8.x4.shared.b16 {%0,%1,%2,%3}, [%4];"
               : "=r"(r[0]), "=r"(r[1]), "=r"(r[2]), "=r"(r[3]) : "r"(addr));
}
__device__ __forceinline__ void ldsm_x4_t(uint32_t addr, uint32_t* r) {
  asm volatile("ldmatrix.sync.aligned.m8n8.x4.trans.shared.b16 {%0,%1,%2,%3}, [%4];"
               : "=r"(r[0]), "=r"(r[1]), "=r"(r[2]), "=r"(r[3]) : "r"(addr));
}

__device__ __forceinline__ void mma16816(float* c, const uint32_t* a, const uint32_t* b) {
  asm volatile(
      "mma.sync.aligned.m16n8k16.row.col.f32.bf16.bf16.f32 "
      "{%0,%1,%2,%3}, {%4,%5,%6,%7}, {%8,%9}, {%0,%1,%2,%3};"
      : "+f"(c[0]), "+f"(c[1]), "+f"(c[2]), "+f"(c[3])
      : "r"(a[0]), "r"(a[1]), "r"(a[2]), "r"(a[3]), "r"(b[0]), "r"(b[1]));
}

__device__ __forceinline__ void split_bf16(float x, __nv_bfloat16& hi, __nv_bfloat16& lo) {
  hi = __float2bfloat16(x);
  lo = __float2bfloat16(x - __bfloat162float(hi));
}

__device__ __forceinline__ void sts8(uint32_t addr, __nv_bfloat16 a, __nv_bfloat16 b,
                                     __nv_bfloat16 c, __nv_bfloat16 d) {
  __nv_bfloat162 p0(a, b), p1(c, d);
  asm volatile("st.shared.v2.b32 [%0], {%1, %2};" ::
               "r"(addr), "r"(*(uint32_t*)&p0), "r"(*(uint32_t*)&p1) : "memory");
}

// bf16 tile row format: 128B/row = [hi plane 32 bf16 (64B) | lo plane (64B)], SW128.
__device__ __forceinline__ uint32_t a_frag_addr(uint32_t tb, int mt, int ks, int p, int lid) {
  uint32_t off = (uint32_t)(mt + (lid & 15)) * 128 + p * 64 + ks * 32 + ((lid >> 4) * 16);
  return tb + SWZ(off);
}
__device__ __forceinline__ uint32_t b_frag_addr(uint32_t tb, int nt, int ks, int p, int lid) {
  uint32_t off = (uint32_t)(nt + ((lid >> 4) & 1) * 8 + (lid & 7)) * 128
               + p * 64 + ks * 32 + (((lid >> 3) & 1) * 16);
  return tb + SWZ(off);
}
// V trans tile: rows = s (32 x 128B), cols = 64 d bf16; tile per (plane, d-half).
__device__ __forceinline__ uint32_t v_frag_addr(uint32_t vstage, int half, int nt,
                                                int ks, int p, int lid) {
  uint32_t base = vstage + (uint32_t)(p * 2 + half) * 4096;
  uint32_t row = (uint32_t)(ks * 16 + ((lid >> 3) & 1) * 8 + (lid & 7));
  uint32_t col = (uint32_t)(nt + ((lid >> 4) & 1) * 8) * 2;
  return base + SWZ(row * 128 + col);
}

// ---------------------------------------------------------------------------
// k-chunk(32) compute, 3-term hi/lo, warp tile 32x64 (A/B both standard tiles).
// ---------------------------------------------------------------------------
__device__ __forceinline__ void compute_chunk(
    uint32_t ta, uint32_t tb, int m0, int n0, int lid, float acc[2][8][4]) {
#pragma unroll
  for (int ks = 0; ks < 2; ks++) {
    uint32_t ahi[2][4], alo[2][4], b[4][4];
#pragma unroll
    for (int mi = 0; mi < 2; mi++) {
      ldsm_x4(a_frag_addr(ta, m0 + mi * 16, ks, 0, lid), ahi[mi]);
      ldsm_x4(a_frag_addr(ta, m0 + mi * 16, ks, 1, lid), alo[mi]);
    }
#pragma unroll
    for (int nj = 0; nj < 4; nj++) ldsm_x4(b_frag_addr(tb, n0 + nj * 16, ks, 0, lid), b[nj]);
#pragma unroll
    for (int mi = 0; mi < 2; mi++)
#pragma unroll
      for (int ni = 0; ni < 8; ni++) {
        uint32_t bb[2] = { b[ni >> 1][(ni & 1) * 2], b[ni >> 1][(ni & 1) * 2 + 1] };
        mma16816(acc[mi][ni], ahi[mi], bb);
      }
#pragma unroll
    for (int mi = 0; mi < 2; mi++)
#pragma unroll
      for (int ni = 0; ni < 8; ni++) {
        uint32_t bb[2] = { b[ni >> 1][(ni & 1) * 2], b[ni >> 1][(ni & 1) * 2 + 1] };
        mma16816(acc[mi][ni], alo[mi], bb);
      }
#pragma unroll
    for (int nj = 0; nj < 4; nj++) ldsm_x4(b_frag_addr(tb, n0 + nj * 16, ks, 1, lid), b[nj]);
#pragma unroll
    for (int mi = 0; mi < 2; mi++)
#pragma unroll
      for (int ni = 0; ni < 8; ni++) {
        uint32_t bb[2] = { b[ni >> 1][(ni & 1) * 2], b[ni >> 1][(ni & 1) * 2 + 1] };
        mma16816(acc[mi][ni], ahi[mi], bb);
      }
  }
}

// Same but B from V trans tiles (half = warp_n selects 64-wide d-half).
__device__ __forceinline__ void compute_chunk_pv(
    uint32_t ta, uint32_t tv, int m0, int half, int lid, float acc[2][8][4]) {
#pragma unroll
  for (int ks = 0; ks < 2; ks++) {
    uint32_t ahi[2][4], alo[2][4], b[4][4];
#pragma unroll
    for (int mi = 0; mi < 2; mi++) {
      ldsm_x4(a_frag_addr(ta, m0 + mi * 16, ks, 0, lid), ahi[mi]);
      ldsm_x4(a_frag_addr(ta, m0 + mi * 16, ks, 1, lid), alo[mi]);
    }
#pragma unroll
    for (int nj = 0; nj < 4; nj++) ldsm_x4_t(v_frag_addr(tv, half, nj * 16, ks, 0, lid), b[nj]);
#pragma unroll
    for (int mi = 0; mi < 2; mi++)
#pragma unroll
      for (int ni = 0; ni < 8; ni++) {
        uint32_t bb[2] = { b[ni >> 1][(ni & 1) * 2], b[ni >> 1][(ni & 1) * 2 + 1] };
        mma16816(acc[mi][ni], ahi[mi], bb);
      }
#pragma unroll
    for (int mi = 0; mi < 2; mi++)
#pragma unroll
      for (int ni = 0; ni < 8; ni++) {
        uint32_t bb[2] = { b[ni >> 1][(ni & 1) * 2], b[ni >> 1][(ni & 1) * 2 + 1] };
        mma16816(acc[mi][ni], alo[mi], bb);
      }
#pragma unroll
    for (int nj = 0; nj < 4; nj++) ldsm_x4_t(v_frag_addr(tv, half, nj * 16, ks, 1, lid), b[nj]);
#pragma unroll
    for (int mi = 0; mi < 2; mi++)
#pragma unroll
      for (int ni = 0; ni < 8; ni++) {
        uint32_t bb[2] = { b[ni >> 1][(ni & 1) * 2], b[ni >> 1][(ni & 1) * 2 + 1] };
        mma16816(acc[mi][ni], ahi[mi], bb);
      }
  }
}

// ---------------------------------------------------------------------------
// JAX threefry2x32 (20 rounds) — exact; partitionable counter layout.
// ---------------------------------------------------------------------------
__device__ __forceinline__ uint32_t rotl32(uint32_t x, int r) {
  return (x << r) | (x >> (32 - r));
}
__device__ __forceinline__ void threefry2x32(uint32_t k0, uint32_t k1,
                                             uint32_t& x0, uint32_t& x1) {
  const uint32_t ks0 = k0, ks1 = k1, ks2 = k0 ^ k1 ^ 0x1BD11BDAu;
  x0 += ks0; x1 += ks1;
#define TF_R(r) { x0 += x1; x1 = rotl32(x1, r); x1 ^= x0; }
  TF_R(13) TF_R(15) TF_R(26) TF_R(6)
  x0 += ks1; x1 += ks2 + 1u;
  TF_R(17) TF_R(29) TF_R(16) TF_R(24)
  x0 += ks2; x1 += ks0 + 2u;
  TF_R(13) TF_R(15) TF_R(26) TF_R(6)
  x0 += ks0; x1 += ks1 + 3u;
  TF_R(17) TF_R(29) TF_R(16) TF_R(24)
  x0 += ks1; x1 += ks2 + 4u;
  TF_R(13) TF_R(15) TF_R(26) TF_R(6)
  x0 += ks2; x1 += ks0 + 5u;
#undef TF_R
}
__device__ __forceinline__ bool keep_draw(uint32_t i) {
  uint32_t x0 = 0u, x1 = i;
  threefry2x32(0u, 42u, x0, x1);
  const uint32_t bits = x0 ^ x1;
  const float u = __uint_as_float((bits >> 9) | 0x3F800000u) - 1.0f;
  return u < 0.1f;
}

// ===========================================================================
// QKS kernel: QK^T + scale + mask + softmax + dropout -> P hi/lo planes.
// Grid (2, HH), 512 threads. fp32 staged via cp.async, converted in smem.
// SMEM: F0 0 | F1 49152 | T0 98304 | T1 147456 ; each stage: A +0, B +16384.
// ===========================================================================
#define QF(s) (sbase + (uint32_t)(s) * 49152u)
#define QT(s) (sbase + 98304u + (uint32_t)(s) * 49152u)
#define QKS_SMEM 196608

__device__ __forceinline__ void qks_cp(
    uint32_t fbase, const float* __restrict__ Qf, const float* __restrict__ Kf,
    size_t qrow0, size_t krow0, int kb, int tid) {
#pragma unroll
  for (int i = 0; i < 6; i++) {
    int seg = tid + i * 512;            // 0..3071 : 1024 A + 2048 B
    int tile = (seg >= 1024);
    int w = tile ? seg - 1024 : seg;
    int r = w >> 3, c4 = w & 7;
    const float* g = tile ? (Kf + (krow0 + r) * DD) : (Qf + (qrow0 + r) * DD);
    cp_async16(fbase + (tile ? 16384u : 0u) + (uint32_t)w * 16u, g + kb + c4 * 4);
  }
  cp_commit();
}

__device__ __forceinline__ void qks_convert(uint32_t fbase, uint32_t tbase, int tid) {
#pragma unroll
  for (int i = 0; i < 6; i++) {
    int seg = tid + i * 512;
    int tile = (seg >= 1024);
    int w = tile ? seg - 1024 : seg;
    uint32_t faddr = fbase + (tile ? 16384u : 0u) + (uint32_t)w * 16u;
    float4 v;
    asm volatile("ld.shared.v4.b32 {%0,%1,%2,%3}, [%4];"
                 : "=f"(v.x), "=f"(v.y), "=f"(v.z), "=f"(v.w) : "r"(faddr));
    __nv_bfloat16 h0, h1, h2, h3, l0, l1, l2, l3;
    split_bf16(v.x, h0, l0); split_bf16(v.y, h1, l1);
    split_bf16(v.z, h2, l2); split_bf16(v.w, h3, l3);
    int r = w >> 3, c4 = w & 7;
    uint32_t tb = tbase + (tile ? 16384u : 0u);
    uint32_t ohi = (uint32_t)r * 128u + (uint32_t)c4 * 8u;
    sts8(tb + SWZ(ohi), h0, h1, h2, h3);
    sts8(tb + SWZ(ohi + 64u), l0, l1, l2, l3);
  }
}

__global__ __launch_bounds__(512, 1) void qks_kernel(
    const float* __restrict__ Qf, const float* __restrict__ Kf,
    const float* __restrict__ mask,
    __nv_bfloat16* __restrict__ phi, __nv_bfloat16* __restrict__ plo) {
  extern __shared__ char smem[];
  const uint32_t sbase = smem_to_u32(smem);
  const int tid = threadIdx.x, wid = tid >> 5, lid = tid & 31;
  const int warp_m = wid >> 2, warp_n = wid & 3;
  const int m0 = warp_m * 32, n0 = warp_n * 64;
  const int q0 = blockIdx.x * 128;
  const int h = blockIdx.y;

  const size_t qrow0 = (size_t)h * SS + q0;
  const size_t krow0 = (size_t)h * SS;

  float acc[2][8][4];
#pragma unroll
  for (int mi = 0; mi < 2; mi++)
#pragma unroll
    for (int ni = 0; ni < 8; ni++)
#pragma unroll
      for (int j = 0; j < 4; j++) acc[mi][ni][j] = 0.0f;

  const int NC = DD / 32;  // 64
  qks_cp(QF(0), Qf, Kf, qrow0, krow0, 0, tid);
  qks_cp(QF(1), Qf, Kf, qrow0, krow0, 32, tid);
  cp_wait1();
  qks_convert(QF(0), QT(0), tid);
  __syncthreads();

  for (int ck = 0; ck < NC; ck++) {
    const bool have2 = (ck + 2 < NC);
    if (have2) qks_cp(QF(ck & 1), Qf, Kf, qrow0, krow0, (ck + 2) * 32, tid);
    const uint32_t ts = QT(ck & 1);
    compute_chunk(ts, ts + 16384u, m0, n0, lid, acc);
    if (ck + 1 < NC) {
      if (have2) cp_wait1(); else cp_wait0();
      qks_convert(QF((ck + 1) & 1), QT((ck + 1) & 1), tid);
    }
    __syncthreads();
  }

  // ---- epilogue: scale + mask ----
  const float scale = 0.022097086912079608f;  // 1/sqrt(2048)
  const int rr = lid >> 2, cc = lid & 3;
#pragma unroll
  for (int mi = 0; mi < 2; mi++)
#pragma unroll
    for (int ni = 0; ni < 8; ni++)
#pragma unroll
      for (int j = 0; j < 4; j++) {
        const int r = q0 + m0 + mi * 16 + (j >> 1) * 8 + rr;
        const int c = n0 + ni * 8 + cc * 2 + (j & 1);
        acc[mi][ni][j] = acc[mi][ni][j] * scale + mask[(size_t)r * SS + c];
      }

  // ---- row softmax across 4 n-warps ----
  float* sred = (float*)smem;  // [128 rows][4]
  float rmax[2][2], rsum[2][2];
#pragma unroll
  for (int mi = 0; mi < 2; mi++)
#pragma unroll
    for (int hf = 0; hf < 2; hf++) {
      float m = -3.4e38f;
#pragma unroll
      for (int ni = 0; ni < 8; ni++) {
        m = fmaxf(m, acc[mi][ni][hf * 2 + 0]);
        m = fmaxf(m, acc[mi][ni][hf * 2 + 1]);
      }
      m = fmaxf(m, __shfl_xor_sync(0xffffffffu, m, 1));
      m = fmaxf(m, __shfl_xor_sync(0xffffffffu, m, 2));
      if (cc == 0) sred[(m0 + mi * 16 + hf * 8 + rr) * 4 + warp_n] = m;
    }
  __syncthreads();
#pragma unroll
  for (int mi = 0; mi < 2; mi++)
#pragma unroll
    for (int hf = 0; hf < 2; hf++) {
      const int row = m0 + mi * 16 + hf * 8 + rr;
      rmax[mi][hf] = fmaxf(fmaxf(sred[row * 4 + 0], sred[row * 4 + 1]),
                           fmaxf(sred[row * 4 + 2], sred[row * 4 + 3]));
    }
  __syncthreads();
#pragma unroll
  for (int mi = 0; mi < 2; mi++)
#pragma unroll
    for (int hf = 0; hf < 2; hf++) {
      float s = 0.0f;
#pragma unroll
      for (int ni = 0; ni < 8; ni++) {
        float e0 = expf(acc[mi][ni][hf * 2 + 0] - rmax[mi][hf]);
        float e1 = expf(acc[mi][ni][hf * 2 + 1] - rmax[mi][hf]);
        acc[mi][ni][hf * 2 + 0] = e0;
        acc[mi][ni][hf * 2 + 1] = e1;
        s += e0 + e1;
      }
      s += __shfl_xor_sync(0xffffffffu, s, 1);
      s += __shfl_xor_sync(0xffffffffu, s, 2);
      if (cc == 0) sred[(m0 + mi * 16 + hf * 8 + rr) * 4 + warp_n] = s;
    }
  __syncthreads();
#pragma unroll
  for (int mi = 0; mi < 2; mi++)
#pragma unroll
    for (int hf = 0; hf < 2; hf++) {
      const int row = m0 + mi * 16 + hf * 8 + rr;
      rsum[mi][hf] = sred[row * 4 + 0] + sred[row * 4 + 1] +
                     sred[row * 4 + 2] + sred[row * 4 + 3];
    }

  // ---- dropout + split + store P planes ----
#pragma unroll
  for (int mi = 0; mi < 2; mi++)
#pragma unroll
    for (int hf = 0; hf < 2; hf++) {
      const int r = q0 + m0 + mi * 16 + hf * 8 + rr;
      const float inv = 1.0f / rsum[mi][hf];
      const uint32_t ibase = ((uint32_t)h * SS + (uint32_t)r) * SS;
#pragma unroll
      for (int ni = 0; ni < 8; ni++) {
        const int c = n0 + ni * 8 + cc * 2;
        float p0 = acc[mi][ni][hf * 2 + 0] * inv;
        float p1 = acc[mi][ni][hf * 2 + 1] * inv;
        p0 = keep_draw(ibase + c)     ? (p0 / 0.1f) : 0.0f;
        p1 = keep_draw(ibase + c + 1) ? (p1 / 0.1f) : 0.0f;
        __nv_bfloat16 h0, h1, l0, l1;
        split_bf16(p0, h0, l0); split_bf16(p1, h1, l1);
        const size_t o = ((size_t)h * SS + r) * SS + c;
        *(__nv_bfloat162*)(phi + o) = __nv_bfloat162(h0, h1);
        *(__nv_bfloat162*)(plo + o) = __nv_bfloat162(l0, l1);
      }
    }
}

// ===========================================================================
// PV kernel: out[h, q0..+128, d0..+128] = P @ V, V fp32 via trans-ldmatrix.
// Grid (16, 2, HH), 256 threads, 2 CTAs/SM.
// SMEM: TA0 0 | TA1 16384 | TA2 32768 | FV0 49152 | FV1 65536
//       TV0 81920 | TV1 98304 ; total 114688.
// ===========================================================================
#define PTA(s) (sbase + (uint32_t)(s) * 16384u)
#define PFV(s) (sbase + 49152u + (uint32_t)(s) * 16384u)
#define PTV(s) (sbase + 81920u + (uint32_t)(s) * 16384u)
#define PV_SMEM 114688

__device__ __forceinline__ void pv_cp(
    uint32_t ta, uint32_t fv,
    const __nv_bfloat16* __restrict__ Phi, const __nv_bfloat16* __restrict__ Plo,
    size_t prow0, const float* __restrict__ Vf, size_t vrow0, int kb, int tid) {
  // P A-tile: 1024 x 16B
#pragma unroll
  for (int i = 0; i < 4; i++) {
    int w = tid + i * 256;
    int r = w >> 3, c = w & 7;
    int p = c >> 2, c16 = c & 3;
    const __nv_bfloat16* g = p ? Plo : Phi;
    cp_async16(ta + SWZ((uint32_t)r * 128u + (uint32_t)p * 64u + (uint32_t)c16 * 16u),
               g + (prow0 + r) * SS + kb + c16 * 8);
  }
  // V fp32: 1024 x 16B, rows = s(32) x 128 d
#pragma unroll
  for (int i = 0; i < 4; i++) {
    int w = tid + i * 256;
    int s = w >> 5, d4 = w & 31;
    cp_async16(fv + (uint32_t)w * 16u, Vf + (vrow0 + kb + s) * DD + d4 * 4);
  }
  cp_commit();
}

__device__ __forceinline__ void pv_vconvert(uint32_t fv, uint32_t tv, int tid) {
#pragma unroll
  for (int i = 0; i < 4; i++) {
    int w = tid + i * 256;
    int s = w >> 5, d4 = w & 31;
    uint32_t faddr = fv + (uint32_t)w * 16u;
    float4 v;
    asm volatile("ld.shared.v4.b32 {%0,%1,%2,%3}, [%4];"
                 : "=f"(v.x), "=f"(v.y), "=f"(v.z), "=f"(v.w) : "r"(faddr));
    __nv_bfloat16 h0, h1, h2, h3, l0, l1, l2, l3;
    split_bf16(v.x, h0, l0); split_bf16(v.y, h1, l1);
    split_bf16(v.z, h2, l2); split_bf16(v.w, h3, l3);
    int half = d4 >> 4, dl4 = d4 & 15;
    uint32_t off = SWZ((uint32_t)s * 128u + (uint32_t)dl4 * 8u);
    sts8(tv + (uint32_t)(0 * 2 + half) * 4096u + off, h0, h1, h2, h3);
    sts8(tv + (uint32_t)(1 * 2 + half) * 4096u + off, l0, l1, l2, l3);
  }
}

__global__ __launch_bounds__(256, 2) void pv_kernel(
    const __nv_bfloat16* __restrict__ Phi, const __nv_bfloat16* __restrict__ Plo,
    const float* __restrict__ Vf, float* __restrict__ out) {
  extern __shared__ char smem[];
  const uint32_t sbase = smem_to_u32(smem);
  const int tid = threadIdx.x, wid = tid >> 5, lid = tid & 31;
  const int warp_m = wid >> 1, warp_n = wid & 1;
  const int d0 = blockIdx.x * 128;
  const int q0 = blockIdx.y * 128;
  const int h = blockIdx.z;

  const size_t prow0 = (size_t)h * SS + q0;
  const size_t vrow0 = (size_t)h * SS;

  float acc[2][8][4];
#pragma unroll
  for (int mi = 0; mi < 2; mi++)
#pragma unroll
    for (int ni = 0; ni < 8; ni++)
#pragma unroll
      for (int j = 0; j < 4; j++) acc[mi][ni][j] = 0.0f;

  const float* Vd = Vf + d0;
  const int NC = SS / 32;  // 8
  pv_cp(PTA(0), PFV(0), Phi, Plo, prow0, Vd, vrow0, 0, tid);
  pv_cp(PTA(1), PFV(1), Phi, Plo, prow0, Vd, vrow0, 32, tid);
  cp_wait1();
  pv_vconvert(PFV(0), PTV(0), tid);
  __syncthreads();

  for (int ck = 0; ck < NC; ck++) {
    const bool have2 = (ck + 2 < NC);
    if (have2)
      pv_cp(PTA((ck + 2) % 3), PFV(ck & 1), Phi, Plo, prow0, Vd, vrow0, (ck + 2) * 32, tid);
    compute_chunk_pv(PTA(ck % 3), PTV(ck & 1), warp_m * 32, warp_n, lid, acc);
    if (ck + 1 < NC) {
      if (have2) cp_wait1(); else cp_wait0();
      pv_vconvert(PFV((ck + 1) & 1), PTV((ck + 1) & 1), tid);
    }
    __syncthreads();
  }

#pragma unroll
  for (int mi = 0; mi < 2; mi++) {
    const int r0 = q0 + warp_m * 32 + mi * 16 + (lid >> 2);
#pragma unroll
    for (int ni = 0; ni < 8; ni++) {
      const int c = d0 + warp_n * 64 + ni * 8 + (lid & 3) * 2;
#pragma unroll
      for (int half = 0; half < 2; half++) {
        const int r = r0 + half * 8;
        *(float2*)(out + ((size_t)h * SS + r) * DD + c) =
            make_float2(acc[mi][ni][half * 2 + 0], acc[mi][ni][half * 2 + 1]);
      }
    }
  }
}

// ---------------------------------------------------------------------------
// Launch
// ---------------------------------------------------------------------------
extern "C" void kernel_launch(void* const* d_in, const int* in_sizes, int n_in,
                              void* d_out, int out_size) {
  const float* Q = (const float*)d_in[0];
  const float* K = (const float*)d_in[1];
  const float* V = (const float*)d_in[2];
  const float* mask = (const float*)d_in[3];
  float* out = (float*)d_out;

  __nv_bfloat16 *phi, *plo;
  cudaGetSymbolAddress((void**)&phi, g_phi);
  cudaGetSymbolAddress((void**)&plo, g_plo);

  cudaFuncSetAttribute(qks_kernel, cudaFuncAttributeMaxDynamicSharedMemorySize, QKS_SMEM);
  cudaFuncSetAttribute(pv_kernel, cudaFuncAttributeMaxDynamicSharedMemorySize, PV_SMEM);

  // QK^T -> scale+mask -> softmax -> dropout -> P hi/lo
  qks_kernel<<<dim3(2, HH), 512, QKS_SMEM>>>(Q, K, mask, phi, plo);
  // P @ V (V read as fp32, trans-ldmatrix)
  pv_kernel<<<dim3(DD / 128, 2, HH), 256, PV_SMEM>>>(phi, plo, V, out);
}

// round 8
// speedup vs baseline: 4.7724x; 1.3811x over previous
#include <cuda_runtime.h>
#include <cuda_fp16.h>
#include <cstdint>

// B=1, H=128, S=256, D=2048, fp32 in/out.
#define HH 128
#define SS 256
#define DD 2048

// ---------------------------------------------------------------------------
// Device scratch (no allocs allowed anywhere).
// ---------------------------------------------------------------------------
__device__ __half g_phi[(size_t)HH * SS * SS];    // P hi [h,q,s]
__device__ __half g_plo[(size_t)HH * SS * SS];    // P lo

// ---------------------------------------------------------------------------
// Helpers
// ---------------------------------------------------------------------------
__device__ __forceinline__ uint32_t smem_to_u32(const void* p) {
  uint32_t a;
  asm("{ .reg .u64 t; cvta.to.shared.u64 t, %1; cvt.u32.u64 %0, t; }" : "=r"(a) : "l"(p));
  return a;
}
#define SWZ(o) ((o) ^ (((o) >> 3) & 0x70))

__device__ __forceinline__ void cp_async16(uint32_t dst, const void* src) {
  asm volatile("cp.async.cg.shared.global [%0], [%1], 16;" :: "r"(dst), "l"(src) : "memory");
}
__device__ __forceinline__ void cp_commit() {
  asm volatile("cp.async.commit_group;" ::: "memory");
}
__device__ __forceinline__ void cp_wait0() {
  asm volatile("cp.async.wait_group 0;" ::: "memory");
}
__device__ __forceinline__ void cp_wait1() {
  asm volatile("cp.async.wait_group 1;" ::: "memory");
}

__device__ __forceinline__ void ldsm_x4(uint32_t addr, uint32_t* r) {
  asm volatile("ldmatrix.sync.aligned.m8n8.x4.shared.b16 {%0,%1,%2,%3}, [%4];"
               : "=r"(r[0]), "=r"(r[1]), "=r"(r[2]), "=r"(r[3]) : "r"(addr));
}
__device__ __forceinline__ void ldsm_x4_t(uint32_t addr, uint32_t* r) {
  asm volatile("ldmatrix.sync.aligned.m8n8.x4.trans.shared.b16 {%0,%1,%2,%3}, [%4];"
               : "=r"(r[0]), "=r"(r[1]), "=r"(r[2]), "=r"(r[3]) : "r"(addr));
}

__device__ __forceinline__ void mma16816(float* c, const uint32_t* a, const uint32_t* b) {
  asm volatile(
      "mma.sync.aligned.m16n8k16.row.col.f32.f16.f16.f32 "
      "{%0,%1,%2,%3}, {%4,%5,%6,%7}, {%8,%9}, {%0,%1,%2,%3};"
      : "+f"(c[0]), "+f"(c[1]), "+f"(c[2]), "+f"(c[3])
      : "r"(a[0]), "r"(a[1]), "r"(a[2]), "r"(a[3]), "r"(b[0]), "r"(b[1]));
}

__device__ __forceinline__ void split_f16(float x, __half& hi, __half& lo) {
  hi = __float2half(x);
  lo = __float2half(x - __half2float(hi));
}

__device__ __forceinline__ void sts8h(uint32_t addr, __half a, __half b,
                                      __half c, __half d) {
  __half2 p0(a, b), p1(c, d);
  asm volatile("st.shared.v2.b32 [%0], {%1, %2};" ::
               "r"(addr), "r"(*(uint32_t*)&p0), "r"(*(uint32_t*)&p1) : "memory");
}

// A tile rows: 128B = [hi 32 fp16 (64B) | lo (64B)], SW128.
__device__ __forceinline__ uint32_t a_frag_addr(uint32_t tb, int mt, int ks, int p, int lid) {
  uint32_t off = (uint32_t)(mt + (lid & 15)) * 128 + p * 64 + ks * 32 + ((lid >> 4) * 16);
  return tb + SWZ(off);
}
// B tile rows: 128B = [chunk-even 32 fp16 | chunk-odd 32 fp16] (hi only), SW128.
// p = chunk parity selects the 64B half.
__device__ __forceinline__ uint32_t b_frag_addr(uint32_t tb, int nt, int ks, int p, int lid) {
  uint32_t off = (uint32_t)(nt + ((lid >> 4) & 1) * 8 + (lid & 7)) * 128
               + p * 64 + ks * 32 + (((lid >> 3) & 1) * 16);
  return tb + SWZ(off);
}
// V trans window tile: per d-half 64 s-rows x 128B (64 d fp16). half at +8192.
__device__ __forceinline__ uint32_t v_frag_addr(uint32_t tvw, int half, int nt,
                                                int ks, int ckp, int lid) {
  uint32_t base = tvw + (uint32_t)half * 8192u;
  uint32_t row = (uint32_t)(ckp * 32 + ks * 16 + ((lid >> 3) & 1) * 8 + (lid & 7));
  uint32_t col = (uint32_t)(nt + ((lid >> 4) & 1) * 8) * 2;
  return base + SWZ(row * 128 + col);
}

// ---------------------------------------------------------------------------
// k-chunk(32) compute, 2-term (ahi*b + alo*b), warp tile 32x64.
// ---------------------------------------------------------------------------
__device__ __forceinline__ void compute_chunk_qk(
    uint32_t ta, uint32_t tb, int pb, int m0, int n0, int lid, float acc[2][8][4]) {
#pragma unroll
  for (int ks = 0; ks < 2; ks++) {
    uint32_t ahi[2][4], alo[2][4], b[4][4];
#pragma unroll
    for (int mi = 0; mi < 2; mi++) {
      ldsm_x4(a_frag_addr(ta, m0 + mi * 16, ks, 0, lid), ahi[mi]);
      ldsm_x4(a_frag_addr(ta, m0 + mi * 16, ks, 1, lid), alo[mi]);
    }
#pragma unroll
    for (int nj = 0; nj < 4; nj++) ldsm_x4(b_frag_addr(tb, n0 + nj * 16, ks, pb, lid), b[nj]);
#pragma unroll
    for (int mi = 0; mi < 2; mi++)
#pragma unroll
      for (int ni = 0; ni < 8; ni++) {
        uint32_t bb[2] = { b[ni >> 1][(ni & 1) * 2], b[ni >> 1][(ni & 1) * 2 + 1] };
        mma16816(acc[mi][ni], ahi[mi], bb);
      }
#pragma unroll
    for (int mi = 0; mi < 2; mi++)
#pragma unroll
      for (int ni = 0; ni < 8; ni++) {
        uint32_t bb[2] = { b[ni >> 1][(ni & 1) * 2], b[ni >> 1][(ni & 1) * 2 + 1] };
        mma16816(acc[mi][ni], alo[mi], bb);
      }
  }
}

__device__ __forceinline__ void compute_chunk_pv(
    uint32_t ta, uint32_t tvw, int ckp, int m0, int half, int lid, float acc[2][8][4]) {
#pragma unroll
  for (int ks = 0; ks < 2; ks++) {
    uint32_t ahi[2][4], alo[2][4], b[4][4];
#pragma unroll
    for (int mi = 0; mi < 2; mi++) {
      ldsm_x4(a_frag_addr(ta, m0 + mi * 16, ks, 0, lid), ahi[mi]);
      ldsm_x4(a_frag_addr(ta, m0 + mi * 16, ks, 1, lid), alo[mi]);
    }
#pragma unroll
    for (int nj = 0; nj < 4; nj++)
      ldsm_x4_t(v_frag_addr(tvw, half, nj * 16, ks, ckp, lid), b[nj]);
#pragma unroll
    for (int mi = 0; mi < 2; mi++)
#pragma unroll
      for (int ni = 0; ni < 8; ni++) {
        uint32_t bb[2] = { b[ni >> 1][(ni & 1) * 2], b[ni >> 1][(ni & 1) * 2 + 1] };
        mma16816(acc[mi][ni], ahi[mi], bb);
      }
#pragma unroll
    for (int mi = 0; mi < 2; mi++)
#pragma unroll
      for (int ni = 0; ni < 8; ni++) {
        uint32_t bb[2] = { b[ni >> 1][(ni & 1) * 2], b[ni >> 1][(ni & 1) * 2 + 1] };
        mma16816(acc[mi][ni], alo[mi], bb);
      }
  }
}

// ---------------------------------------------------------------------------
// JAX threefry2x32 (20 rounds) — exact; partitionable counter layout.
// ---------------------------------------------------------------------------
__device__ __forceinline__ uint32_t rotl32(uint32_t x, int r) {
  return (x << r) | (x >> (32 - r));
}
__device__ __forceinline__ void threefry2x32(uint32_t k0, uint32_t k1,
                                             uint32_t& x0, uint32_t& x1) {
  const uint32_t ks0 = k0, ks1 = k1, ks2 = k0 ^ k1 ^ 0x1BD11BDAu;
  x0 += ks0; x1 += ks1;
#define TF_R(r) { x0 += x1; x1 = rotl32(x1, r); x1 ^= x0; }
  TF_R(13) TF_R(15) TF_R(26) TF_R(6)
  x0 += ks1; x1 += ks2 + 1u;
  TF_R(17) TF_R(29) TF_R(16) TF_R(24)
  x0 += ks2; x1 += ks0 + 2u;
  TF_R(13) TF_R(15) TF_R(26) TF_R(6)
  x0 += ks0; x1 += ks1 + 3u;
  TF_R(17) TF_R(29) TF_R(16) TF_R(24)
  x0 += ks1; x1 += ks2 + 4u;
  TF_R(13) TF_R(15) TF_R(26) TF_R(6)
  x0 += ks2; x1 += ks0 + 5u;
#undef TF_R
}
__device__ __forceinline__ bool keep_draw(uint32_t i) {
  uint32_t x0 = 0u, x1 = i;
  threefry2x32(0u, 42u, x0, x1);
  const uint32_t bits = x0 ^ x1;
  const float u = __uint_as_float((bits >> 9) | 0x3F800000u) - 1.0f;
  return u < 0.1f;
}

// ===========================================================================
// QKS kernel: QK^T + scale + mask + softmax + dropout -> P hi/lo planes.
// Grid (2, HH), 512 threads.
// SMEM: fp32 stages QF(0..1) 2x48KB @0 ; A fp16 QA(0..1) 2x16KB @98304 ;
//       B fp16 windows QB(0..1) 2x32KB @131072. Total 192KB.
// ===========================================================================
#define QF(s) (sbase + (uint32_t)(s) * 49152u)
#define QA(s) (sbase + 98304u + (uint32_t)(s) * 16384u)
#define QB(w) (sbase + 131072u + (uint32_t)(w) * 32768u)
#define QKS_SMEM 196608

__device__ __forceinline__ void qks_cp(
    uint32_t fbase, const float* __restrict__ Qf, const float* __restrict__ Kf,
    size_t qrow0, size_t krow0, int kb, int tid) {
#pragma unroll
  for (int i = 0; i < 6; i++) {
    int seg = tid + i * 512;            // 0..3071 : 1024 A + 2048 B
    int tile = (seg >= 1024);
    int w = tile ? seg - 1024 : seg;
    int r = w >> 3, c4 = w & 7;
    const float* g = tile ? (Kf + (krow0 + r) * DD) : (Qf + (qrow0 + r) * DD);
    cp_async16(fbase + (tile ? 16384u : 0u) + (uint32_t)w * 16u, g + kb + c4 * 4);
  }
  cp_commit();
}

__device__ __forceinline__ void qks_convert(uint32_t fbase, uint32_t taA,
                                            uint32_t tbB, int pb, int tid) {
#pragma unroll
  for (int i = 0; i < 6; i++) {
    int seg = tid + i * 512;
    int tile = (seg >= 1024);
    int w = tile ? seg - 1024 : seg;
    uint32_t faddr = fbase + (tile ? 16384u : 0u) + (uint32_t)w * 16u;
    float4 v;
    asm volatile("ld.shared.v4.b32 {%0,%1,%2,%3}, [%4];"
                 : "=f"(v.x), "=f"(v.y), "=f"(v.z), "=f"(v.w) : "r"(faddr));
    int r = w >> 3, c4 = w & 7;
    if (tile == 0) {
      __half h0, h1, h2, h3, l0, l1, l2, l3;
      split_f16(v.x, h0, l0); split_f16(v.y, h1, l1);
      split_f16(v.z, h2, l2); split_f16(v.w, h3, l3);
      uint32_t ohi = (uint32_t)r * 128u + (uint32_t)c4 * 8u;
      sts8h(taA + SWZ(ohi), h0, h1, h2, h3);
      sts8h(taA + SWZ(ohi + 64u), l0, l1, l2, l3);
    } else {
      __half h0 = __float2half(v.x), h1 = __float2half(v.y);
      __half h2 = __float2half(v.z), h3 = __float2half(v.w);
      uint32_t o = (uint32_t)r * 128u + (uint32_t)pb * 64u + (uint32_t)c4 * 8u;
      sts8h(tbB + SWZ(o), h0, h1, h2, h3);
    }
  }
}

__global__ __launch_bounds__(512, 1) void qks_kernel(
    const float* __restrict__ Qf, const float* __restrict__ Kf,
    const float* __restrict__ mask,
    __half* __restrict__ phi, __half* __restrict__ plo) {
  extern __shared__ char smem[];
  const uint32_t sbase = smem_to_u32(smem);
  const int tid = threadIdx.x, wid = tid >> 5, lid = tid & 31;
  const int warp_m = wid >> 2, warp_n = wid & 3;
  const int m0 = warp_m * 32, n0 = warp_n * 64;
  const int q0 = blockIdx.x * 128;
  const int h = blockIdx.y;

  const size_t qrow0 = (size_t)h * SS + q0;
  const size_t krow0 = (size_t)h * SS;

  float acc[2][8][4];
#pragma unroll
  for (int mi = 0; mi < 2; mi++)
#pragma unroll
    for (int ni = 0; ni < 8; ni++)
#pragma unroll
      for (int j = 0; j < 4; j++) acc[mi][ni][j] = 0.0f;

  const int NC = DD / 32;  // 64
  qks_cp(QF(0), Qf, Kf, qrow0, krow0, 0, tid);
  qks_cp(QF(1), Qf, Kf, qrow0, krow0, 32, tid);
  cp_wait1();
  qks_convert(QF(0), QA(0), QB(0), 0, tid);
  __syncthreads();

  for (int ck = 0; ck < NC; ck++) {
    const bool have2 = (ck + 2 < NC);
    if (have2) qks_cp(QF(ck & 1), Qf, Kf, qrow0, krow0, (ck + 2) * 32, tid);
    compute_chunk_qk(QA(ck & 1), QB((ck >> 1) & 1), ck & 1, m0, n0, lid, acc);
    if (ck + 1 < NC) {
      if (have2) cp_wait1(); else cp_wait0();
      qks_convert(QF((ck + 1) & 1), QA((ck + 1) & 1), QB(((ck + 1) >> 1) & 1),
                  (ck + 1) & 1, tid);
    }
    __syncthreads();
  }

  // ---- epilogue: scale + mask ----
  const float scale = 0.022097086912079608f;  // 1/sqrt(2048)
  const int rr = lid >> 2, cc = lid & 3;
#pragma unroll
  for (int mi = 0; mi < 2; mi++)
#pragma unroll
    for (int ni = 0; ni < 8; ni++)
#pragma unroll
      for (int j = 0; j < 4; j++) {
        const int r = q0 + m0 + mi * 16 + (j >> 1) * 8 + rr;
        const int c = n0 + ni * 8 + cc * 2 + (j & 1);
        acc[mi][ni][j] = acc[mi][ni][j] * scale + mask[(size_t)r * SS + c];
      }

  // ---- row softmax across 4 n-warps ----
  float* sred = (float*)smem;  // [128 rows][4]
  float rmax[2][2], rsum[2][2];
#pragma unroll
  for (int mi = 0; mi < 2; mi++)
#pragma unroll
    for (int hf = 0; hf < 2; hf++) {
      float m = -3.4e38f;
#pragma unroll
      for (int ni = 0; ni < 8; ni++) {
        m = fmaxf(m, acc[mi][ni][hf * 2 + 0]);
        m = fmaxf(m, acc[mi][ni][hf * 2 + 1]);
      }
      m = fmaxf(m, __shfl_xor_sync(0xffffffffu, m, 1));
      m = fmaxf(m, __shfl_xor_sync(0xffffffffu, m, 2));
      if (cc == 0) sred[(m0 + mi * 16 + hf * 8 + rr) * 4 + warp_n] = m;
    }
  __syncthreads();
#pragma unroll
  for (int mi = 0; mi < 2; mi++)
#pragma unroll
    for (int hf = 0; hf < 2; hf++) {
      const int row = m0 + mi * 16 + hf * 8 + rr;
      rmax[mi][hf] = fmaxf(fmaxf(sred[row * 4 + 0], sred[row * 4 + 1]),
                           fmaxf(sred[row * 4 + 2], sred[row * 4 + 3]));
    }
  __syncthreads();
#pragma unroll
  for (int mi = 0; mi < 2; mi++)
#pragma unroll
    for (int hf = 0; hf < 2; hf++) {
      float s = 0.0f;
#pragma unroll
      for (int ni = 0; ni < 8; ni++) {
        float e0 = expf(acc[mi][ni][hf * 2 + 0] - rmax[mi][hf]);
        float e1 = expf(acc[mi][ni][hf * 2 + 1] - rmax[mi][hf]);
        acc[mi][ni][hf * 2 + 0] = e0;
        acc[mi][ni][hf * 2 + 1] = e1;
        s += e0 + e1;
      }
      s += __shfl_xor_sync(0xffffffffu, s, 1);
      s += __shfl_xor_sync(0xffffffffu, s, 2);
      if (cc == 0) sred[(m0 + mi * 16 + hf * 8 + rr) * 4 + warp_n] = s;
    }
  __syncthreads();
#pragma unroll
  for (int mi = 0; mi < 2; mi++)
#pragma unroll
    for (int hf = 0; hf < 2; hf++) {
      const int row = m0 + mi * 16 + hf * 8 + rr;
      rsum[mi][hf] = sred[row * 4 + 0] + sred[row * 4 + 1] +
                     sred[row * 4 + 2] + sred[row * 4 + 3];
    }

  // ---- dropout + split + store P planes ----
#pragma unroll
  for (int mi = 0; mi < 2; mi++)
#pragma unroll
    for (int hf = 0; hf < 2; hf++) {
      const int r = q0 + m0 + mi * 16 + hf * 8 + rr;
      const float inv = 1.0f / rsum[mi][hf];
      const uint32_t ibase = ((uint32_t)h * SS + (uint32_t)r) * SS;
#pragma unroll
      for (int ni = 0; ni < 8; ni++) {
        const int c = n0 + ni * 8 + cc * 2;
        float p0 = acc[mi][ni][hf * 2 + 0] * inv;
        float p1 = acc[mi][ni][hf * 2 + 1] * inv;
        p0 = keep_draw(ibase + c)     ? (p0 / 0.1f) : 0.0f;
        p1 = keep_draw(ibase + c + 1) ? (p1 / 0.1f) : 0.0f;
        __half h0, h1, l0, l1;
        split_f16(p0, h0, l0); split_f16(p1, h1, l1);
        const size_t o = ((size_t)h * SS + r) * SS + c;
        *(__half2*)(phi + o) = __half2(h0, h1);
        *(__half2*)(plo + o) = __half2(l0, l1);
      }
    }
}

// ===========================================================================
// PV kernel: out[h, q0..+128, d0..+128] = P @ V (V fp32 -> fp16 hi via trans).
// Grid (16, 2, HH), 256 threads, 2 CTAs/SM.
// SMEM: PTA(0..2) 3x16KB @0 ; PFV(0..1) 2x16KB @49152 ; PTV(0..1) 2x16KB @81920.
// Total 112KB.
// ===========================================================================
#define PTA(s) (sbase + (uint32_t)(s) * 16384u)
#define PFV(s) (sbase + 49152u + (uint32_t)(s) * 16384u)
#define PTV(w) (sbase + 81920u + (uint32_t)(w) * 16384u)
#define PV_SMEM 114688

__device__ __forceinline__ void pv_cp(
    uint32_t ta, uint32_t fv,
    const __half* __restrict__ Phi, const __half* __restrict__ Plo,
    size_t prow0, const float* __restrict__ Vf, size_t vrow0, int kb, int tid) {
  // P A-tile: 1024 x 16B ([hi|lo] rows)
#pragma unroll
  for (int i = 0; i < 4; i++) {
    int w = tid + i * 256;
    int r = w >> 3, c = w & 7;
    int p = c >> 2, c16 = c & 3;
    const __half* g = p ? Plo : Phi;
    cp_async16(ta + SWZ((uint32_t)r * 128u + (uint32_t)p * 64u + (uint32_t)c16 * 16u),
               g + (prow0 + r) * SS + kb + c16 * 8);
  }
  // V fp32: 1024 x 16B, 32 s-rows x 128 d
#pragma unroll
  for (int i = 0; i < 4; i++) {
    int w = tid + i * 256;
    int s = w >> 5, d4 = w & 31;
    cp_async16(fv + (uint32_t)w * 16u, Vf + (vrow0 + kb + s) * DD + d4 * 4);
  }
  cp_commit();
}

__device__ __forceinline__ void pv_vconvert(uint32_t fv, uint32_t tvw, int ckp, int tid) {
#pragma unroll
  for (int i = 0; i < 4; i++) {
    int w = tid + i * 256;
    int s = w >> 5, d4 = w & 31;
    uint32_t faddr = fv + (uint32_t)w * 16u;
    float4 v;
    asm volatile("ld.shared.v4.b32 {%0,%1,%2,%3}, [%4];"
                 : "=f"(v.x), "=f"(v.y), "=f"(v.z), "=f"(v.w) : "r"(faddr));
    __half h0 = __float2half(v.x), h1 = __float2half(v.y);
    __half h2 = __float2half(v.z), h3 = __float2half(v.w);
    int half = d4 >> 4, dl4 = d4 & 15;
    uint32_t off = SWZ(((uint32_t)(ckp * 32 + s)) * 128u + (uint32_t)dl4 * 8u);
    sts8h(tvw + (uint32_t)half * 8192u + off, h0, h1, h2, h3);
  }
}

__global__ __launch_bounds__(256, 2) void pv_kernel(
    const __half* __restrict__ Phi, const __half* __restrict__ Plo,
    const float* __restrict__ Vf, float* __restrict__ out) {
  extern __shared__ char smem[];
  const uint32_t sbase = smem_to_u32(smem);
  const int tid = threadIdx.x, wid = tid >> 5, lid = tid & 31;
  const int warp_m = wid >> 1, warp_n = wid & 1;
  const int d0 = blockIdx.x * 128;
  const int q0 = blockIdx.y * 128;
  const int h = blockIdx.z;

  const size_t prow0 = (size_t)h * SS + q0;
  const size_t vrow0 = (size_t)h * SS;

  float acc[2][8][4];
#pragma unroll
  for (int mi = 0; mi < 2; mi++)
#pragma unroll
    for (int ni = 0; ni < 8; ni++)
#pragma unroll
      for (int j = 0; j < 4; j++) acc[mi][ni][j] = 0.0f;

  const float* Vd = Vf + d0;
  const int NC = SS / 32;  // 8
  pv_cp(PTA(0), PFV(0), Phi, Plo, prow0, Vd, vrow0, 0, tid);
  pv_cp(PTA(1), PFV(1), Phi, Plo, prow0, Vd, vrow0, 32, tid);
  cp_wait1();
  pv_vconvert(PFV(0), PTV(0), 0, tid);
  __syncthreads();

  for (int ck = 0; ck < NC; ck++) {
    const bool have2 = (ck + 2 < NC);
    if (have2)
      pv_cp(PTA((ck + 2) % 3), PFV(ck & 1), Phi, Plo, prow0, Vd, vrow0, (ck + 2) * 32, tid);
    compute_chunk_pv(PTA(ck % 3), PTV((ck >> 1) & 1), ck & 1,
                     warp_m * 32, warp_n, lid, acc);
    if (ck + 1 < NC) {
      if (have2) cp_wait1(); else cp_wait0();
      pv_vconvert(PFV((ck + 1) & 1), PTV(((ck + 1) >> 1) & 1), (ck + 1) & 1, tid);
    }
    __syncthreads();
  }

#pragma unroll
  for (int mi = 0; mi < 2; mi++) {
    const int r0 = q0 + warp_m * 32 + mi * 16 + (lid >> 2);
#pragma unroll
    for (int ni = 0; ni < 8; ni++) {
      const int c = d0 + warp_n * 64 + ni * 8 + (lid & 3) * 2;
#pragma unroll
      for (int half = 0; half < 2; half++) {
        const int r = r0 + half * 8;
        *(float2*)(out + ((size_t)h * SS + r) * DD + c) =
            make_float2(acc[mi][ni][half * 2 + 0], acc[mi][ni][half * 2 + 1]);
      }
    }
  }
}

// ---------------------------------------------------------------------------
// Launch
// ---------------------------------------------------------------------------
extern "C" void kernel_launch(void* const* d_in, const int* in_sizes, int n_in,
                              void* d_out, int out_size) {
  const float* Q = (const float*)d_in[0];
  const float* K = (const float*)d_in[1];
  const float* V = (const float*)d_in[2];
  const float* mask = (const float*)d_in[3];
  float* out = (float*)d_out;

  __half *phi, *plo;
  cudaGetSymbolAddress((void**)&phi, g_phi);
  cudaGetSymbolAddress((void**)&plo, g_plo);

  cudaFuncSetAttribute(qks_kernel, cudaFuncAttributeMaxDynamicSharedMemorySize, QKS_SMEM);
  cudaFuncSetAttribute(pv_kernel, cudaFuncAttributeMaxDynamicSharedMemorySize, PV_SMEM);

  // QK^T -> scale+mask -> softmax -> dropout -> P hi/lo (fp16, 2-term MMA)
  qks_kernel<<<dim3(2, HH), 512, QKS_SMEM>>>(Q, K, mask, phi, plo);
  // P @ V (V fp16 hi-only, trans-ldmatrix; P 2-term)
  pv_kernel<<<dim3(DD / 128, 2, HH), 256, PV_SMEM>>>(phi, plo, V, out);
}

// round 9
// speedup vs baseline: 5.4749x; 1.1472x over previous
#include <cuda_runtime.h>
#include <cuda_fp16.h>
#include <cstdint>

// B=1, H=128, S=256, D=2048, fp32 in/out.
#define HH 128
#define SS 256
#define DD 2048

// ---------------------------------------------------------------------------
// Device scratch (no allocs allowed anywhere).
// ---------------------------------------------------------------------------
__device__ __half g_phi[(size_t)HH * SS * SS];    // P fp16 [h,q,s]

// ---------------------------------------------------------------------------
// Helpers
// ---------------------------------------------------------------------------
__device__ __forceinline__ uint32_t smem_to_u32(const void* p) {
  uint32_t a;
  asm("{ .reg .u64 t; cvta.to.shared.u64 t, %1; cvt.u32.u64 %0, t; }" : "=r"(a) : "l"(p));
  return a;
}
#define SWZ(o) ((o) ^ (((o) >> 3) & 0x70))

__device__ __forceinline__ void cp_async16(uint32_t dst, const void* src) {
  asm volatile("cp.async.cg.shared.global [%0], [%1], 16;" :: "r"(dst), "l"(src) : "memory");
}
__device__ __forceinline__ void cp_commit() {
  asm volatile("cp.async.commit_group;" ::: "memory");
}
__device__ __forceinline__ void cp_wait0() {
  asm volatile("cp.async.wait_group 0;" ::: "memory");
}
__device__ __forceinline__ void cp_wait1() {
  asm volatile("cp.async.wait_group 1;" ::: "memory");
}

__device__ __forceinline__ void ldsm_x4(uint32_t addr, uint32_t* r) {
  asm volatile("ldmatrix.sync.aligned.m8n8.x4.shared.b16 {%0,%1,%2,%3}, [%4];"
               : "=r"(r[0]), "=r"(r[1]), "=r"(r[2]), "=r"(r[3]) : "r"(addr));
}
__device__ __forceinline__ void ldsm_x4_t(uint32_t addr, uint32_t* r) {
  asm volatile("ldmatrix.sync.aligned.m8n8.x4.trans.shared.b16 {%0,%1,%2,%3}, [%4];"
               : "=r"(r[0]), "=r"(r[1]), "=r"(r[2]), "=r"(r[3]) : "r"(addr));
}

__device__ __forceinline__ void mma16816(float* c, const uint32_t* a, const uint32_t* b) {
  asm volatile(
      "mma.sync.aligned.m16n8k16.row.col.f32.f16.f16.f32 "
      "{%0,%1,%2,%3}, {%4,%5,%6,%7}, {%8,%9}, {%0,%1,%2,%3};"
      : "+f"(c[0]), "+f"(c[1]), "+f"(c[2]), "+f"(c[3])
      : "r"(a[0]), "r"(a[1]), "r"(a[2]), "r"(a[3]), "r"(b[0]), "r"(b[1]));
}

__device__ __forceinline__ void split_f16(float x, __half& hi, __half& lo) {
  hi = __float2half(x);
  lo = __float2half(x - __half2float(hi));
}

__device__ __forceinline__ void sts8h(uint32_t addr, __half a, __half b,
                                      __half c, __half d) {
  __half2 p0(a, b), p1(c, d);
  asm volatile("st.shared.v2.b32 [%0], {%1, %2};" ::
               "r"(addr), "r"(*(uint32_t*)&p0), "r"(*(uint32_t*)&p1) : "memory");
}

// A tile rows (qks A): 128B = [hi 32 fp16 (64B) | lo (64B)], SW128.
// For windowed hi-only tiles (qks B, pv A), p = chunk parity selects the half.
__device__ __forceinline__ uint32_t a_frag_addr(uint32_t tb, int mt, int ks, int p, int lid) {
  uint32_t off = (uint32_t)(mt + (lid & 15)) * 128 + p * 64 + ks * 32 + ((lid >> 4) * 16);
  return tb + SWZ(off);
}
__device__ __forceinline__ uint32_t b_frag_addr(uint32_t tb, int nt, int ks, int p, int lid) {
  uint32_t off = (uint32_t)(nt + ((lid >> 4) & 1) * 8 + (lid & 7)) * 128
               + p * 64 + ks * 32 + (((lid >> 3) & 1) * 16);
  return tb + SWZ(off);
}
// V trans window tile: per d-half 64 s-rows x 128B (64 d fp16). half at +8192.
__device__ __forceinline__ uint32_t v_frag_addr(uint32_t tvw, int half, int nt,
                                                int ks, int ckp, int lid) {
  uint32_t base = tvw + (uint32_t)half * 8192u;
  uint32_t row = (uint32_t)(ckp * 32 + ks * 16 + ((lid >> 3) & 1) * 8 + (lid & 7));
  uint32_t col = (uint32_t)(nt + ((lid >> 4) & 1) * 8) * 2;
  return base + SWZ(row * 128 + col);
}

// ---------------------------------------------------------------------------
// qks k-chunk(32): 2-term (A hi + A lo) x B hi, warp tile 32x64.
// ---------------------------------------------------------------------------
__device__ __forceinline__ void compute_chunk_qk(
    uint32_t ta, uint32_t tb, int pb, int m0, int n0, int lid, float acc[2][8][4]) {
#pragma unroll
  for (int ks = 0; ks < 2; ks++) {
    uint32_t ahi[2][4], alo[2][4], b[4][4];
#pragma unroll
    for (int mi = 0; mi < 2; mi++) {
      ldsm_x4(a_frag_addr(ta, m0 + mi * 16, ks, 0, lid), ahi[mi]);
      ldsm_x4(a_frag_addr(ta, m0 + mi * 16, ks, 1, lid), alo[mi]);
    }
#pragma unroll
    for (int nj = 0; nj < 4; nj++) ldsm_x4(b_frag_addr(tb, n0 + nj * 16, ks, pb, lid), b[nj]);
#pragma unroll
    for (int mi = 0; mi < 2; mi++)
#pragma unroll
      for (int ni = 0; ni < 8; ni++) {
        uint32_t bb[2] = { b[ni >> 1][(ni & 1) * 2], b[ni >> 1][(ni & 1) * 2 + 1] };
        mma16816(acc[mi][ni], ahi[mi], bb);
      }
#pragma unroll
    for (int mi = 0; mi < 2; mi++)
#pragma unroll
      for (int ni = 0; ni < 8; ni++) {
        uint32_t bb[2] = { b[ni >> 1][(ni & 1) * 2], b[ni >> 1][(ni & 1) * 2 + 1] };
        mma16816(acc[mi][ni], alo[mi], bb);
      }
  }
}

// pv k-chunk(32): 1-term (P hi) x (V hi via trans), warp tile 32x64.
__device__ __forceinline__ void compute_chunk_pv(
    uint32_t taw, int pa, uint32_t tvw, int ckp, int m0, int half, int lid,
    float acc[2][8][4]) {
#pragma unroll
  for (int ks = 0; ks < 2; ks++) {
    uint32_t a[2][4], b[4][4];
#pragma unroll
    for (int mi = 0; mi < 2; mi++)
      ldsm_x4(a_frag_addr(taw, m0 + mi * 16, ks, pa, lid), a[mi]);
#pragma unroll
    for (int nj = 0; nj < 4; nj++)
      ldsm_x4_t(v_frag_addr(tvw, half, nj * 16, ks, ckp, lid), b[nj]);
#pragma unroll
    for (int mi = 0; mi < 2; mi++)
#pragma unroll
      for (int ni = 0; ni < 8; ni++) {
        uint32_t bb[2] = { b[ni >> 1][(ni & 1) * 2], b[ni >> 1][(ni & 1) * 2 + 1] };
        mma16816(acc[mi][ni], a[mi], bb);
      }
  }
}

// ---------------------------------------------------------------------------
// JAX threefry2x32 (20 rounds) — exact; partitionable counter layout.
// ---------------------------------------------------------------------------
__device__ __forceinline__ uint32_t rotl32(uint32_t x, int r) {
  return (x << r) | (x >> (32 - r));
}
__device__ __forceinline__ void threefry2x32(uint32_t k0, uint32_t k1,
                                             uint32_t& x0, uint32_t& x1) {
  const uint32_t ks0 = k0, ks1 = k1, ks2 = k0 ^ k1 ^ 0x1BD11BDAu;
  x0 += ks0; x1 += ks1;
#define TF_R(r) { x0 += x1; x1 = rotl32(x1, r); x1 ^= x0; }
  TF_R(13) TF_R(15) TF_R(26) TF_R(6)
  x0 += ks1; x1 += ks2 + 1u;
  TF_R(17) TF_R(29) TF_R(16) TF_R(24)
  x0 += ks2; x1 += ks0 + 2u;
  TF_R(13) TF_R(15) TF_R(26) TF_R(6)
  x0 += ks0; x1 += ks1 + 3u;
  TF_R(17) TF_R(29) TF_R(16) TF_R(24)
  x0 += ks1; x1 += ks2 + 4u;
  TF_R(13) TF_R(15) TF_R(26) TF_R(6)
  x0 += ks2; x1 += ks0 + 5u;
#undef TF_R
}
__device__ __forceinline__ bool keep_draw(uint32_t i) {
  uint32_t x0 = 0u, x1 = i;
  threefry2x32(0u, 42u, x0, x1);
  const uint32_t bits = x0 ^ x1;
  const float u = __uint_as_float((bits >> 9) | 0x3F800000u) - 1.0f;
  return u < 0.1f;
}

// ===========================================================================
// QKS kernel: QK^T + scale + mask + softmax + dropout -> P fp16.
// Grid (2, HH), 512 threads.
// SMEM: fp32 stages QF(0..1) 2x48KB @0 ; A fp16 QA(0..1) 2x16KB @98304 ;
//       B fp16 windows QB(0..1) 2x32KB @131072. Total 192KB.
// ===========================================================================
#define QF(s) (sbase + (uint32_t)(s) * 49152u)
#define QA(s) (sbase + 98304u + (uint32_t)(s) * 16384u)
#define QB(w) (sbase + 131072u + (uint32_t)(w) * 32768u)
#define QKS_SMEM 196608

__device__ __forceinline__ void qks_cp(
    uint32_t fbase, const float* __restrict__ Qf, const float* __restrict__ Kf,
    size_t qrow0, size_t krow0, int kb, int tid) {
#pragma unroll
  for (int i = 0; i < 6; i++) {
    int seg = tid + i * 512;            // 0..3071 : 1024 A + 2048 B
    int tile = (seg >= 1024);
    int w = tile ? seg - 1024 : seg;
    int r = w >> 3, c4 = w & 7;
    const float* g = tile ? (Kf + (krow0 + r) * DD) : (Qf + (qrow0 + r) * DD);
    cp_async16(fbase + (tile ? 16384u : 0u) + (uint32_t)w * 16u, g + kb + c4 * 4);
  }
  cp_commit();
}

__device__ __forceinline__ void qks_convert(uint32_t fbase, uint32_t taA,
                                            uint32_t tbB, int pb, int tid) {
#pragma unroll
  for (int i = 0; i < 6; i++) {
    int seg = tid + i * 512;
    int tile = (seg >= 1024);
    int w = tile ? seg - 1024 : seg;
    uint32_t faddr = fbase + (tile ? 16384u : 0u) + (uint32_t)w * 16u;
    float4 v;
    asm volatile("ld.shared.v4.b32 {%0,%1,%2,%3}, [%4];"
                 : "=f"(v.x), "=f"(v.y), "=f"(v.z), "=f"(v.w) : "r"(faddr));
    int r = w >> 3, c4 = w & 7;
    if (tile == 0) {
      __half h0, h1, h2, h3, l0, l1, l2, l3;
      split_f16(v.x, h0, l0); split_f16(v.y, h1, l1);
      split_f16(v.z, h2, l2); split_f16(v.w, h3, l3);
      uint32_t ohi = (uint32_t)r * 128u + (uint32_t)c4 * 8u;
      sts8h(taA + SWZ(ohi), h0, h1, h2, h3);
      sts8h(taA + SWZ(ohi + 64u), l0, l1, l2, l3);
    } else {
      __half h0 = __float2half(v.x), h1 = __float2half(v.y);
      __half h2 = __float2half(v.z), h3 = __float2half(v.w);
      uint32_t o = (uint32_t)r * 128u + (uint32_t)pb * 64u + (uint32_t)c4 * 8u;
      sts8h(tbB + SWZ(o), h0, h1, h2, h3);
    }
  }
}

__global__ __launch_bounds__(512, 1) void qks_kernel(
    const float* __restrict__ Qf, const float* __restrict__ Kf,
    const float* __restrict__ mask, __half* __restrict__ phi) {
  extern __shared__ char smem[];
  const uint32_t sbase = smem_to_u32(smem);
  const int tid = threadIdx.x, wid = tid >> 5, lid = tid & 31;
  const int warp_m = wid >> 2, warp_n = wid & 3;
  const int m0 = warp_m * 32, n0 = warp_n * 64;
  const int q0 = blockIdx.x * 128;
  const int h = blockIdx.y;

  const size_t qrow0 = (size_t)h * SS + q0;
  const size_t krow0 = (size_t)h * SS;

  float acc[2][8][4];
#pragma unroll
  for (int mi = 0; mi < 2; mi++)
#pragma unroll
    for (int ni = 0; ni < 8; ni++)
#pragma unroll
      for (int j = 0; j < 4; j++) acc[mi][ni][j] = 0.0f;

  const int NC = DD / 32;  // 64
  qks_cp(QF(0), Qf, Kf, qrow0, krow0, 0, tid);
  qks_cp(QF(1), Qf, Kf, qrow0, krow0, 32, tid);
  cp_wait1();
  qks_convert(QF(0), QA(0), QB(0), 0, tid);
  __syncthreads();

  for (int ck = 0; ck < NC; ck++) {
    const bool have2 = (ck + 2 < NC);
    if (have2) qks_cp(QF(ck & 1), Qf, Kf, qrow0, krow0, (ck + 2) * 32, tid);
    compute_chunk_qk(QA(ck & 1), QB((ck >> 1) & 1), ck & 1, m0, n0, lid, acc);
    if (ck + 1 < NC) {
      if (have2) cp_wait1(); else cp_wait0();
      qks_convert(QF((ck + 1) & 1), QA((ck + 1) & 1), QB(((ck + 1) >> 1) & 1),
                  (ck + 1) & 1, tid);
    }
    __syncthreads();
  }

  // ---- epilogue: scale + mask ----
  const float scale = 0.022097086912079608f;  // 1/sqrt(2048)
  const int rr = lid >> 2, cc = lid & 3;
#pragma unroll
  for (int mi = 0; mi < 2; mi++)
#pragma unroll
    for (int ni = 0; ni < 8; ni++)
#pragma unroll
      for (int j = 0; j < 4; j++) {
        const int r = q0 + m0 + mi * 16 + (j >> 1) * 8 + rr;
        const int c = n0 + ni * 8 + cc * 2 + (j & 1);
        acc[mi][ni][j] = acc[mi][ni][j] * scale + mask[(size_t)r * SS + c];
      }

  // ---- row softmax across 4 n-warps ----
  float* sred = (float*)smem;  // [128 rows][4]
  float rmax[2][2], rsum[2][2];
#pragma unroll
  for (int mi = 0; mi < 2; mi++)
#pragma unroll
    for (int hf = 0; hf < 2; hf++) {
      float m = -3.4e38f;
#pragma unroll
      for (int ni = 0; ni < 8; ni++) {
        m = fmaxf(m, acc[mi][ni][hf * 2 + 0]);
        m = fmaxf(m, acc[mi][ni][hf * 2 + 1]);
      }
      m = fmaxf(m, __shfl_xor_sync(0xffffffffu, m, 1));
      m = fmaxf(m, __shfl_xor_sync(0xffffffffu, m, 2));
      if (cc == 0) sred[(m0 + mi * 16 + hf * 8 + rr) * 4 + warp_n] = m;
    }
  __syncthreads();
#pragma unroll
  for (int mi = 0; mi < 2; mi++)
#pragma unroll
    for (int hf = 0; hf < 2; hf++) {
      const int row = m0 + mi * 16 + hf * 8 + rr;
      rmax[mi][hf] = fmaxf(fmaxf(sred[row * 4 + 0], sred[row * 4 + 1]),
                           fmaxf(sred[row * 4 + 2], sred[row * 4 + 3]));
    }
  __syncthreads();
#pragma unroll
  for (int mi = 0; mi < 2; mi++)
#pragma unroll
    for (int hf = 0; hf < 2; hf++) {
      float s = 0.0f;
#pragma unroll
      for (int ni = 0; ni < 8; ni++) {
        float e0 = expf(acc[mi][ni][hf * 2 + 0] - rmax[mi][hf]);
        float e1 = expf(acc[mi][ni][hf * 2 + 1] - rmax[mi][hf]);
        acc[mi][ni][hf * 2 + 0] = e0;
        acc[mi][ni][hf * 2 + 1] = e1;
        s += e0 + e1;
      }
      s += __shfl_xor_sync(0xffffffffu, s, 1);
      s += __shfl_xor_sync(0xffffffffu, s, 2);
      if (cc == 0) sred[(m0 + mi * 16 + hf * 8 + rr) * 4 + warp_n] = s;
    }
  __syncthreads();
#pragma unroll
  for (int mi = 0; mi < 2; mi++)
#pragma unroll
    for (int hf = 0; hf < 2; hf++) {
      const int row = m0 + mi * 16 + hf * 8 + rr;
      rsum[mi][hf] = sred[row * 4 + 0] + sred[row * 4 + 1] +
                     sred[row * 4 + 2] + sred[row * 4 + 3];
    }

  // ---- dropout + fp16 store ----
#pragma unroll
  for (int mi = 0; mi < 2; mi++)
#pragma unroll
    for (int hf = 0; hf < 2; hf++) {
      const int r = q0 + m0 + mi * 16 + hf * 8 + rr;
      const float inv = 1.0f / rsum[mi][hf];
      const uint32_t ibase = ((uint32_t)h * SS + (uint32_t)r) * SS;
#pragma unroll
      for (int ni = 0; ni < 8; ni++) {
        const int c = n0 + ni * 8 + cc * 2;
        float p0 = acc[mi][ni][hf * 2 + 0] * inv;
        float p1 = acc[mi][ni][hf * 2 + 1] * inv;
        p0 = keep_draw(ibase + c)     ? (p0 / 0.1f) : 0.0f;
        p1 = keep_draw(ibase + c + 1) ? (p1 / 0.1f) : 0.0f;
        const size_t o = ((size_t)h * SS + r) * SS + c;
        *(__half2*)(phi + o) = __half2(__float2half(p0), __float2half(p1));
      }
    }
}

// ===========================================================================
// PV kernel: out[h, q0..+128, d0..+128] = P @ V (both fp16 hi-only, 1-term).
// Grid (16, 2, HH), 256 threads, 2 CTAs/SM.
// SMEM: PA windows(0..1) 2x16KB @0 ; PFV(0..1) 2x16KB @32768 ;
//       PTV windows(0..1) 2x16KB @65536. Total 96KB.
// ===========================================================================
#define PA(w)  (sbase + (uint32_t)(w) * 16384u)
#define PFV(s) (sbase + 32768u + (uint32_t)(s) * 16384u)
#define PTV(w) (sbase + 65536u + (uint32_t)(w) * 16384u)
#define PV_SMEM 98304

__device__ __forceinline__ void pv_cp(
    uint32_t paw, int pb, uint32_t fv,
    const __half* __restrict__ Phi, size_t prow0,
    const float* __restrict__ Vf, size_t vrow0, int kb, int tid) {
  // P A hi tile: 512 x 16B into window half pb
#pragma unroll
  for (int i = 0; i < 2; i++) {
    int w = tid + i * 256;              // 0..511
    int r = w >> 2, c16 = w & 3;
    cp_async16(paw + SWZ((uint32_t)r * 128u + (uint32_t)pb * 64u + (uint32_t)c16 * 16u),
               Phi + (prow0 + r) * SS + kb + c16 * 8);
  }
  // V fp32: 1024 x 16B, 32 s-rows x 128 d
#pragma unroll
  for (int i = 0; i < 4; i++) {
    int w = tid + i * 256;
    int s = w >> 5, d4 = w & 31;
    cp_async16(fv + (uint32_t)w * 16u, Vf + (vrow0 + kb + s) * DD + d4 * 4);
  }
  cp_commit();
}

__device__ __forceinline__ void pv_vconvert(uint32_t fv, uint32_t tvw, int ckp, int tid) {
#pragma unroll
  for (int i = 0; i < 4; i++) {
    int w = tid + i * 256;
    int s = w >> 5, d4 = w & 31;
    uint32_t faddr = fv + (uint32_t)w * 16u;
    float4 v;
    asm volatile("ld.shared.v4.b32 {%0,%1,%2,%3}, [%4];"
                 : "=f"(v.x), "=f"(v.y), "=f"(v.z), "=f"(v.w) : "r"(faddr));
    __half h0 = __float2half(v.x), h1 = __float2half(v.y);
    __half h2 = __float2half(v.z), h3 = __float2half(v.w);
    int half = d4 >> 4, dl4 = d4 & 15;
    uint32_t off = SWZ(((uint32_t)(ckp * 32 + s)) * 128u + (uint32_t)dl4 * 8u);
    sts8h(tvw + (uint32_t)half * 8192u + off, h0, h1, h2, h3);
  }
}

__global__ __launch_bounds__(256, 2) void pv_kernel(
    const __half* __restrict__ Phi, const float* __restrict__ Vf,
    float* __restrict__ out) {
  extern __shared__ char smem[];
  const uint32_t sbase = smem_to_u32(smem);
  const int tid = threadIdx.x, wid = tid >> 5, lid = tid & 31;
  const int warp_m = wid >> 1, warp_n = wid & 1;
  const int d0 = blockIdx.x * 128;
  const int q0 = blockIdx.y * 128;
  const int h = blockIdx.z;

  const size_t prow0 = (size_t)h * SS + q0;
  const size_t vrow0 = (size_t)h * SS;

  float acc[2][8][4];
#pragma unroll
  for (int mi = 0; mi < 2; mi++)
#pragma unroll
    for (int ni = 0; ni < 8; ni++)
#pragma unroll
      for (int j = 0; j < 4; j++) acc[mi][ni][j] = 0.0f;

  const float* Vd = Vf + d0;
  const int NC = SS / 32;  // 8
  pv_cp(PA(0), 0, PFV(0), Phi, prow0, Vd, vrow0, 0, tid);
  pv_cp(PA(0), 1, PFV(1), Phi, prow0, Vd, vrow0, 32, tid);
  cp_wait1();
  pv_vconvert(PFV(0), PTV(0), 0, tid);
  __syncthreads();

  for (int ck = 0; ck < NC; ck++) {
    const bool have2 = (ck + 2 < NC);
    if (have2)
      pv_cp(PA(((ck + 2) >> 1) & 1), (ck + 2) & 1, PFV(ck & 1),
            Phi, prow0, Vd, vrow0, (ck + 2) * 32, tid);
    compute_chunk_pv(PA((ck >> 1) & 1), ck & 1, PTV((ck >> 1) & 1), ck & 1,
                     warp_m * 32, warp_n, lid, acc);
    if (ck + 1 < NC) {
      if (have2) cp_wait1(); else cp_wait0();
      pv_vconvert(PFV((ck + 1) & 1), PTV(((ck + 1) >> 1) & 1), (ck + 1) & 1, tid);
    }
    __syncthreads();
  }

#pragma unroll
  for (int mi = 0; mi < 2; mi++) {
    const int r0 = q0 + warp_m * 32 + mi * 16 + (lid >> 2);
#pragma unroll
    for (int ni = 0; ni < 8; ni++) {
      const int c = d0 + warp_n * 64 + ni * 8 + (lid & 3) * 2;
#pragma unroll
      for (int half = 0; half < 2; half++) {
        const int r = r0 + half * 8;
        *(float2*)(out + ((size_t)h * SS + r) * DD + c) =
            make_float2(acc[mi][ni][half * 2 + 0], acc[mi][ni][half * 2 + 1]);
      }
    }
  }
}

// ---------------------------------------------------------------------------
// Launch
// ---------------------------------------------------------------------------
extern "C" void kernel_launch(void* const* d_in, const int* in_sizes, int n_in,
                              void* d_out, int out_size) {
  const float* Q = (const float*)d_in[0];
  const float* K = (const float*)d_in[1];
  const float* V = (const float*)d_in[2];
  const float* mask = (const float*)d_in[3];
  float* out = (float*)d_out;

  __half* phi;
  cudaGetSymbolAddress((void**)&phi, g_phi);

  cudaFuncSetAttribute(qks_kernel, cudaFuncAttributeMaxDynamicSharedMemorySize, QKS_SMEM);
  cudaFuncSetAttribute(pv_kernel, cudaFuncAttributeMaxDynamicSharedMemorySize, PV_SMEM);

  // QK^T -> scale+mask -> softmax -> dropout -> P fp16
  qks_kernel<<<dim3(2, HH), 512, QKS_SMEM>>>(Q, K, mask, phi);
  // P @ V (1-term fp16)
  pv_kernel<<<dim3(DD / 128, 2, HH), 256, PV_SMEM>>>(phi, V, out);
}

// round 10
// speedup vs baseline: 6.2653x; 1.1444x over previous
#include <cuda_runtime.h>
#include <cuda_fp16.h>
#include <cstdint>

// B=1, H=128, S=256, D=2048, fp32 in/out.
#define HH 128
#define SS 256
#define DD 2048

// ---------------------------------------------------------------------------
// Device scratch (no allocs allowed anywhere).
// ---------------------------------------------------------------------------
__device__ __half g_phi[(size_t)HH * SS * SS];    // P fp16 [h,q,s]

// ---------------------------------------------------------------------------
// Helpers
// ---------------------------------------------------------------------------
__device__ __forceinline__ uint32_t smem_to_u32(const void* p) {
  uint32_t a;
  asm("{ .reg .u64 t; cvta.to.shared.u64 t, %1; cvt.u32.u64 %0, t; }" : "=r"(a) : "l"(p));
  return a;
}
#define SWZ(o) ((o) ^ (((o) >> 3) & 0x70))

__device__ __forceinline__ void cp_async16(uint32_t dst, const void* src) {
  asm volatile("cp.async.cg.shared.global [%0], [%1], 16;" :: "r"(dst), "l"(src) : "memory");
}
__device__ __forceinline__ void cp_commit() {
  asm volatile("cp.async.commit_group;" ::: "memory");
}
__device__ __forceinline__ void cp_wait0() {
  asm volatile("cp.async.wait_group 0;" ::: "memory");
}
__device__ __forceinline__ void cp_wait1() {
  asm volatile("cp.async.wait_group 1;" ::: "memory");
}

__device__ __forceinline__ void ldsm_x4(uint32_t addr, uint32_t* r) {
  asm volatile("ldmatrix.sync.aligned.m8n8.x4.shared.b16 {%0,%1,%2,%3}, [%4];"
               : "=r"(r[0]), "=r"(r[1]), "=r"(r[2]), "=r"(r[3]) : "r"(addr));
}
__device__ __forceinline__ void ldsm_x4_t(uint32_t addr, uint32_t* r) {
  asm volatile("ldmatrix.sync.aligned.m8n8.x4.trans.shared.b16 {%0,%1,%2,%3}, [%4];"
               : "=r"(r[0]), "=r"(r[1]), "=r"(r[2]), "=r"(r[3]) : "r"(addr));
}

__device__ __forceinline__ void mma16816(float* c, const uint32_t* a, const uint32_t* b) {
  asm volatile(
      "mma.sync.aligned.m16n8k16.row.col.f32.f16.f16.f32 "
      "{%0,%1,%2,%3}, {%4,%5,%6,%7}, {%8,%9}, {%0,%1,%2,%3};"
      : "+f"(c[0]), "+f"(c[1]), "+f"(c[2]), "+f"(c[3])
      : "r"(a[0]), "r"(a[1]), "r"(a[2]), "r"(a[3]), "r"(b[0]), "r"(b[1]));
}

__device__ __forceinline__ void sts8h(uint32_t addr, __half a, __half b,
                                      __half c, __half d) {
  __half2 p0(a, b), p1(c, d);
  asm volatile("st.shared.v2.b32 [%0], {%1, %2};" ::
               "r"(addr), "r"(*(uint32_t*)&p0), "r"(*(uint32_t*)&p1) : "memory");
}

// Window tile rows: 128B hold 64 k fp16 = two 32-k chunks; p = chunk parity
// selects the 64B half; ks = 16-k step within chunk. SW128 swizzled.
__device__ __forceinline__ uint32_t a_frag_addr(uint32_t tb, int mt, int ks, int p, int lid) {
  uint32_t off = (uint32_t)(mt + (lid & 15)) * 128 + p * 64 + ks * 32 + ((lid >> 4) * 16);
  return tb + SWZ(off);
}
__device__ __forceinline__ uint32_t b_frag_addr(uint32_t tb, int nt, int ks, int p, int lid) {
  uint32_t off = (uint32_t)(nt + ((lid >> 4) & 1) * 8 + (lid & 7)) * 128
               + p * 64 + ks * 32 + (((lid >> 3) & 1) * 16);
  return tb + SWZ(off);
}
// V subtile (per 64-d slice): 256 s-rows x 128B (64 d fp16); trans-ldmatrix B frag.
__device__ __forceinline__ uint32_t v_frag_addr(uint32_t vbase, int krow, int nt, int lid) {
  uint32_t row = (uint32_t)(krow + ((lid >> 3) & 1) * 8 + (lid & 7));
  uint32_t col = (uint32_t)(nt + ((lid >> 4) & 1) * 8) * 2;
  return vbase + SWZ(row * 128 + col);
}

// ---------------------------------------------------------------------------
// qks k-chunk(32): 1-term A hi x B hi, warp tile 32x64.
// ---------------------------------------------------------------------------
__device__ __forceinline__ void compute_chunk_qk(
    uint32_t taw, uint32_t tbw, int p, int m0, int n0, int lid, float acc[2][8][4]) {
#pragma unroll
  for (int ks = 0; ks < 2; ks++) {
    uint32_t a[2][4], b[4][4];
#pragma unroll
    for (int mi = 0; mi < 2; mi++)
      ldsm_x4(a_frag_addr(taw, m0 + mi * 16, ks, p, lid), a[mi]);
#pragma unroll
    for (int nj = 0; nj < 4; nj++)
      ldsm_x4(b_frag_addr(tbw, n0 + nj * 16, ks, p, lid), b[nj]);
#pragma unroll
    for (int mi = 0; mi < 2; mi++)
#pragma unroll
      for (int ni = 0; ni < 8; ni++) {
        uint32_t bb[2] = { b[ni >> 1][(ni & 1) * 2], b[ni >> 1][(ni & 1) * 2 + 1] };
        mma16816(acc[mi][ni], a[mi], bb);
      }
  }
}

// ---------------------------------------------------------------------------
// JAX threefry2x32 (20 rounds) — exact; partitionable counter layout.
// ---------------------------------------------------------------------------
__device__ __forceinline__ uint32_t rotl32(uint32_t x, int r) {
  return (x << r) | (x >> (32 - r));
}
__device__ __forceinline__ void threefry2x32(uint32_t k0, uint32_t k1,
                                             uint32_t& x0, uint32_t& x1) {
  const uint32_t ks0 = k0, ks1 = k1, ks2 = k0 ^ k1 ^ 0x1BD11BDAu;
  x0 += ks0; x1 += ks1;
#define TF_R(r) { x0 += x1; x1 = rotl32(x1, r); x1 ^= x0; }
  TF_R(13) TF_R(15) TF_R(26) TF_R(6)
  x0 += ks1; x1 += ks2 + 1u;
  TF_R(17) TF_R(29) TF_R(16) TF_R(24)
  x0 += ks2; x1 += ks0 + 2u;
  TF_R(13) TF_R(15) TF_R(26) TF_R(6)
  x0 += ks0; x1 += ks1 + 3u;
  TF_R(17) TF_R(29) TF_R(16) TF_R(24)
  x0 += ks1; x1 += ks2 + 4u;
  TF_R(13) TF_R(15) TF_R(26) TF_R(6)
  x0 += ks2; x1 += ks0 + 5u;
#undef TF_R
}
__device__ __forceinline__ bool keep_draw(uint32_t i) {
  uint32_t x0 = 0u, x1 = i;
  threefry2x32(0u, 42u, x0, x1);
  const uint32_t bits = x0 ^ x1;
  const float u = __uint_as_float((bits >> 9) | 0x3F800000u) - 1.0f;
  return u < 0.1f;
}

// ===========================================================================
// QKS kernel: QK^T + scale + mask + softmax + dropout -> P fp16 (1-term).
// Grid (2, HH), 512 threads.
// SMEM: QF(0..1) 2x48KB @0 ; QA windows(0..1) 2x16KB @98304 ;
//       QB windows(0..1) 2x32KB @131072. Total 192KB.
// ===========================================================================
#define QF(s) (sbase + (uint32_t)(s) * 49152u)
#define QA(w) (sbase + 98304u + (uint32_t)(w) * 16384u)
#define QB(w) (sbase + 131072u + (uint32_t)(w) * 32768u)
#define QKS_SMEM 196608

__device__ __forceinline__ void qks_cp(
    uint32_t fbase, const float* __restrict__ Qf, const float* __restrict__ Kf,
    size_t qrow0, size_t krow0, int kb, int tid) {
#pragma unroll
  for (int i = 0; i < 6; i++) {
    int seg = tid + i * 512;            // 0..3071 : 1024 A + 2048 B
    int tile = (seg >= 1024);
    int w = tile ? seg - 1024 : seg;
    int r = w >> 3, c4 = w & 7;
    const float* g = tile ? (Kf + (krow0 + r) * DD) : (Qf + (qrow0 + r) * DD);
    cp_async16(fbase + (tile ? 16384u : 0u) + (uint32_t)w * 16u, g + kb + c4 * 4);
  }
  cp_commit();
}

__device__ __forceinline__ void qks_convert(uint32_t fbase, uint32_t taw,
                                            uint32_t tbw, int p, int tid) {
#pragma unroll
  for (int i = 0; i < 6; i++) {
    int seg = tid + i * 512;
    int tile = (seg >= 1024);
    int w = tile ? seg - 1024 : seg;
    uint32_t faddr = fbase + (tile ? 16384u : 0u) + (uint32_t)w * 16u;
    float4 v;
    asm volatile("ld.shared.v4.b32 {%0,%1,%2,%3}, [%4];"
                 : "=f"(v.x), "=f"(v.y), "=f"(v.z), "=f"(v.w) : "r"(faddr));
    __half h0 = __float2half(v.x), h1 = __float2half(v.y);
    __half h2 = __float2half(v.z), h3 = __float2half(v.w);
    int r = w >> 3, c4 = w & 7;
    uint32_t base = tile ? tbw : taw;
    uint32_t o = (uint32_t)r * 128u + (uint32_t)p * 64u + (uint32_t)c4 * 8u;
    sts8h(base + SWZ(o), h0, h1, h2, h3);
  }
}

__global__ __launch_bounds__(512, 1) void qks_kernel(
    const float* __restrict__ Qf, const float* __restrict__ Kf,
    const float* __restrict__ mask, __half* __restrict__ phi) {
  extern __shared__ char smem[];
  const uint32_t sbase = smem_to_u32(smem);
  const int tid = threadIdx.x, wid = tid >> 5, lid = tid & 31;
  const int warp_m = wid >> 2, warp_n = wid & 3;
  const int m0 = warp_m * 32, n0 = warp_n * 64;
  const int q0 = blockIdx.x * 128;
  const int h = blockIdx.y;

  const size_t qrow0 = (size_t)h * SS + q0;
  const size_t krow0 = (size_t)h * SS;

  float acc[2][8][4];
#pragma unroll
  for (int mi = 0; mi < 2; mi++)
#pragma unroll
    for (int ni = 0; ni < 8; ni++)
#pragma unroll
      for (int j = 0; j < 4; j++) acc[mi][ni][j] = 0.0f;

  const int NC = DD / 32;  // 64
  qks_cp(QF(0), Qf, Kf, qrow0, krow0, 0, tid);
  qks_cp(QF(1), Qf, Kf, qrow0, krow0, 32, tid);
  cp_wait1();
  qks_convert(QF(0), QA(0), QB(0), 0, tid);
  __syncthreads();

  for (int ck = 0; ck < NC; ck++) {
    const bool have2 = (ck + 2 < NC);
    if (have2) qks_cp(QF(ck & 1), Qf, Kf, qrow0, krow0, (ck + 2) * 32, tid);
    compute_chunk_qk(QA((ck >> 1) & 1), QB((ck >> 1) & 1), ck & 1, m0, n0, lid, acc);
    if (ck + 1 < NC) {
      if (have2) cp_wait1(); else cp_wait0();
      qks_convert(QF((ck + 1) & 1), QA(((ck + 1) >> 1) & 1), QB(((ck + 1) >> 1) & 1),
                  (ck + 1) & 1, tid);
    }
    __syncthreads();
  }

  // ---- epilogue: scale + mask ----
  const float scale = 0.022097086912079608f;  // 1/sqrt(2048)
  const int rr = lid >> 2, cc = lid & 3;
#pragma unroll
  for (int mi = 0; mi < 2; mi++)
#pragma unroll
    for (int ni = 0; ni < 8; ni++)
#pragma unroll
      for (int j = 0; j < 4; j++) {
        const int r = q0 + m0 + mi * 16 + (j >> 1) * 8 + rr;
        const int c = n0 + ni * 8 + cc * 2 + (j & 1);
        acc[mi][ni][j] = acc[mi][ni][j] * scale + mask[(size_t)r * SS + c];
      }

  // ---- row softmax across 4 n-warps ----
  float* sred = (float*)smem;  // [128 rows][4]
  float rmax[2][2], rsum[2][2];
#pragma unroll
  for (int mi = 0; mi < 2; mi++)
#pragma unroll
    for (int hf = 0; hf < 2; hf++) {
      float m = -3.4e38f;
#pragma unroll
      for (int ni = 0; ni < 8; ni++) {
        m = fmaxf(m, acc[mi][ni][hf * 2 + 0]);
        m = fmaxf(m, acc[mi][ni][hf * 2 + 1]);
      }
      m = fmaxf(m, __shfl_xor_sync(0xffffffffu, m, 1));
      m = fmaxf(m, __shfl_xor_sync(0xffffffffu, m, 2));
      if (cc == 0) sred[(m0 + mi * 16 + hf * 8 + rr) * 4 + warp_n] = m;
    }
  __syncthreads();
#pragma unroll
  for (int mi = 0; mi < 2; mi++)
#pragma unroll
    for (int hf = 0; hf < 2; hf++) {
      const int row = m0 + mi * 16 + hf * 8 + rr;
      rmax[mi][hf] = fmaxf(fmaxf(sred[row * 4 + 0], sred[row * 4 + 1]),
                           fmaxf(sred[row * 4 + 2], sred[row * 4 + 3]));
    }
  __syncthreads();
#pragma unroll
  for (int mi = 0; mi < 2; mi++)
#pragma unroll
    for (int hf = 0; hf < 2; hf++) {
      float s = 0.0f;
#pragma unroll
      for (int ni = 0; ni < 8; ni++) {
        float e0 = expf(acc[mi][ni][hf * 2 + 0] - rmax[mi][hf]);
        float e1 = expf(acc[mi][ni][hf * 2 + 1] - rmax[mi][hf]);
        acc[mi][ni][hf * 2 + 0] = e0;
        acc[mi][ni][hf * 2 + 1] = e1;
        s += e0 + e1;
      }
      s += __shfl_xor_sync(0xffffffffu, s, 1);
      s += __shfl_xor_sync(0xffffffffu, s, 2);
      if (cc == 0) sred[(m0 + mi * 16 + hf * 8 + rr) * 4 + warp_n] = s;
    }
  __syncthreads();
#pragma unroll
  for (int mi = 0; mi < 2; mi++)
#pragma unroll
    for (int hf = 0; hf < 2; hf++) {
      const int row = m0 + mi * 16 + hf * 8 + rr;
      rsum[mi][hf] = sred[row * 4 + 0] + sred[row * 4 + 1] +
                     sred[row * 4 + 2] + sred[row * 4 + 3];
    }

  // ---- dropout + fp16 store ----
#pragma unroll
  for (int mi = 0; mi < 2; mi++)
#pragma unroll
    for (int hf = 0; hf < 2; hf++) {
      const int r = q0 + m0 + mi * 16 + hf * 8 + rr;
      const float inv = 1.0f / rsum[mi][hf];
      const uint32_t ibase = ((uint32_t)h * SS + (uint32_t)r) * SS;
#pragma unroll
      for (int ni = 0; ni < 8; ni++) {
        const int c = n0 + ni * 8 + cc * 2;
        float p0 = acc[mi][ni][hf * 2 + 0] * inv;
        float p1 = acc[mi][ni][hf * 2 + 1] * inv;
        p0 = keep_draw(ibase + c)     ? (p0 / 0.1f) : 0.0f;
        p1 = keep_draw(ibase + c + 1) ? (p1 / 0.1f) : 0.0f;
        const size_t o = ((size_t)h * SS + r) * SS + c;
        *(__half2*)(phi + o) = __half2(__float2half(p0), __float2half(p1));
      }
    }
}

// ===========================================================================
// PV kernel: out[h, :, d0..+256] = P @ V, V smem-resident, sync-free MMA loop.
// Grid (8, HH), 512 threads, 1 CTA/SM.
// SMEM: V subtiles(0..3) 4x32KB @0 (128KB) ; P windows(0..3) 4x16KB @131072
//       (64KB, doubles as 2x32KB V fp32 staging). Total 192KB.
// ===========================================================================
#define PVV(ds) (sbase + (uint32_t)(ds) * 32768u)
#define PVP(w)  (sbase + 131072u + (uint32_t)(w) * 16384u)
#define PVS(i)  (sbase + 131072u + (uint32_t)(i) * 32768u)
#define PV_SMEM 196608

__global__ __launch_bounds__(512, 1) void pv_kernel(
    const __half* __restrict__ Phi, const float* __restrict__ Vf,
    float* __restrict__ out) {
  extern __shared__ char smem[];
  const uint32_t sbase = smem_to_u32(smem);
  const int tid = threadIdx.x, wid = tid >> 5, lid = tid & 31;
  const int warp_m = wid >> 2, warp_n = wid & 3;   // 4 x 4 warps
  const int m0 = warp_m * 32;
  const int d0 = blockIdx.x * 256;
  const int h = blockIdx.y;

  const size_t vrow0 = (size_t)h * SS;
  const size_t prow0 = (size_t)h * SS;

  // ---- Phase 1: V fp32 -> fp16 trans subtiles, 8 rounds of 32 s-rows ----
  // cp round j into PVS(j&1); convert reads it into PVV subtiles.
  {
    auto cp_round = [&](int j, int buf) {
#pragma unroll
      for (int i = 0; i < 4; i++) {
        int w = tid + i * 512;          // 0..2047
        int sl = w >> 6, d4 = w & 63;
        cp_async16(PVS(buf) + (uint32_t)w * 16u,
                   Vf + (vrow0 + j * 32 + sl) * DD + d0 + d4 * 4);
      }
      cp_commit();
    };
    cp_round(0, 0);
    cp_round(1, 1);
    for (int j = 0; j < 8; j++) {
      if (j + 1 < 8) cp_wait1(); else cp_wait0();
      // convert round j from PVS(j&1)
#pragma unroll
      for (int i = 0; i < 4; i++) {
        int w = tid + i * 512;
        int sl = w >> 6, d4 = w & 63;
        float4 v;
        asm volatile("ld.shared.v4.b32 {%0,%1,%2,%3}, [%4];"
                     : "=f"(v.x), "=f"(v.y), "=f"(v.z), "=f"(v.w)
                     : "r"(PVS(j & 1) + (uint32_t)w * 16u));
        __half h0 = __float2half(v.x), h1 = __float2half(v.y);
        __half h2 = __float2half(v.z), h3 = __float2half(v.w);
        int ds = d4 >> 4, dl4 = d4 & 15;
        int sg = j * 32 + sl;
        sts8h(PVV(ds) + SWZ((uint32_t)sg * 128u + (uint32_t)dl4 * 8u),
              h0, h1, h2, h3);
      }
      __syncthreads();
      if (j + 2 < 8) cp_round(j + 2, j & 1);
    }
  }

  // ---- Phase 2: per q-tile, cp P then sync-free MMA loop ----
  for (int qt = 0; qt < 2; qt++) {
    // cp full 128x256 fp16 P tile into 4 windows
#pragma unroll
    for (int i = 0; i < 8; i++) {
      int w = tid + i * 512;            // 0..4095
      int kbw = w >> 10, rem = w & 1023;
      int r = rem >> 3, c16 = rem & 7;
      cp_async16(PVP(kbw) + SWZ((uint32_t)r * 128u + (uint32_t)c16 * 16u),
                 Phi + (prow0 + qt * 128 + r) * SS + kbw * 64 + c16 * 8);
    }
    cp_commit();
    cp_wait0();
    __syncthreads();

    float acc[2][8][4];
#pragma unroll
    for (int mi = 0; mi < 2; mi++)
#pragma unroll
      for (int ni = 0; ni < 8; ni++)
#pragma unroll
        for (int j = 0; j < 4; j++) acc[mi][ni][j] = 0.0f;

    const uint32_t vb = PVV(warp_n);
#pragma unroll
    for (int kb = 0; kb < 4; kb++) {
#pragma unroll
      for (int p = 0; p < 2; p++) {
#pragma unroll
        for (int ks = 0; ks < 2; ks++) {
          uint32_t a[2][4], b[4][4];
#pragma unroll
          for (int mi = 0; mi < 2; mi++)
            ldsm_x4(a_frag_addr(PVP(kb), m0 + mi * 16, ks, p, lid), a[mi]);
          const int krow = kb * 64 + p * 32 + ks * 16;
#pragma unroll
          for (int nj = 0; nj < 4; nj++)
            ldsm_x4_t(v_frag_addr(vb, krow, nj * 16, lid), b[nj]);
#pragma unroll
          for (int mi = 0; mi < 2; mi++)
#pragma unroll
            for (int ni = 0; ni < 8; ni++) {
              uint32_t bb[2] = { b[ni >> 1][(ni & 1) * 2],
                                 b[ni >> 1][(ni & 1) * 2 + 1] };
              mma16816(acc[mi][ni], a[mi], bb);
            }
        }
      }
    }

    // epilogue: write fp32 out
#pragma unroll
    for (int mi = 0; mi < 2; mi++) {
      const int r0 = qt * 128 + m0 + mi * 16 + (lid >> 2);
#pragma unroll
      for (int ni = 0; ni < 8; ni++) {
        const int c = d0 + warp_n * 64 + ni * 8 + (lid & 3) * 2;
#pragma unroll
        for (int half = 0; half < 2; half++) {
          const int r = r0 + half * 8;
          *(float2*)(out + ((size_t)h * SS + r) * DD + c) =
              make_float2(acc[mi][ni][half * 2 + 0], acc[mi][ni][half * 2 + 1]);
        }
      }
    }
    __syncthreads();  // P windows reused next q-tile
  }
}

// ---------------------------------------------------------------------------
// Launch
// ---------------------------------------------------------------------------
extern "C" void kernel_launch(void* const* d_in, const int* in_sizes, int n_in,
                              void* d_out, int out_size) {
  const float* Q = (const float*)d_in[0];
  const float* K = (const float*)d_in[1];
  const float* V = (const float*)d_in[2];
  const float* mask = (const float*)d_in[3];
  float* out = (float*)d_out;

  __half* phi;
  cudaGetSymbolAddress((void**)&phi, g_phi);

  cudaFuncSetAttribute(qks_kernel, cudaFuncAttributeMaxDynamicSharedMemorySize, QKS_SMEM);
  cudaFuncSetAttribute(pv_kernel, cudaFuncAttributeMaxDynamicSharedMemorySize, PV_SMEM);

  // QK^T -> scale+mask -> softmax -> dropout -> P fp16 (1-term)
  qks_kernel<<<dim3(2, HH), 512, QKS_SMEM>>>(Q, K, mask, phi);
  // P @ V (1-term, V smem-resident)
  pv_kernel<<<dim3(8, HH), 512, PV_SMEM>>>(phi, V, out);
}